// round 11
// baseline (speedup 1.0000x reference)
#include <cuda_runtime.h>
#include <cuda_bf16.h>
#include <cuda_fp16.h>
#include <math.h>
#include <stdint.h>

// ---------------- static scratch (no allocations allowed) ----------------
#define MAXN 100000
#define MAXE 1600000
#define NGRAPH 256

__device__ float  g_bufA[(size_t)MAXN * 128];   // fp32 (N x 128)
__device__ __half g_h1[(size_t)MAXN * 64];      // fp16 gather array (layer1 out)
__device__ __half g_h3[(size_t)MAXN * 64];      // fp16 gather array (gemm3 out)
__device__ float  g_xs[(size_t)MAXN * 5];
__device__ int    g_cnt[MAXN];
__device__ int    g_rowptr[MAXN + 1];
__device__ int    g_curoff[MAXN];
__device__ float  g_dinv[MAXN];
__device__ int    g_col[MAXE];
__device__ int    g_bsums[128];
__device__ float  g_pool[NGRAPH * 64];
__device__ float  g_gcnt[NGRAPH];
__device__ int    g_is64[1];

__device__ __forceinline__ int load_idx(const void* p, long long i, int is64) {
    if (is64) return (int)((const long long*)p)[i];
    return ((const int*)p)[i];
}

__device__ __forceinline__ void split2(float a, float b, uint32_t& hi, uint32_t& lo) {
    __nv_bfloat16 ah = __float2bfloat16(a);
    __nv_bfloat16 bh = __float2bfloat16(b);
    __nv_bfloat16 al = __float2bfloat16(a - __bfloat162float(ah));
    __nv_bfloat16 bl = __float2bfloat16(b - __bfloat162float(bh));
    unsigned short ahu = *(unsigned short*)&ah, bhu = *(unsigned short*)&bh;
    unsigned short alu = *(unsigned short*)&al, blu = *(unsigned short*)&bl;
    hi = ((uint32_t)bhu << 16) | ahu;
    lo = ((uint32_t)blu << 16) | alu;
}

__device__ __forceinline__ void mma16816(float* d, const uint32_t* a,
                                         uint32_t b0, uint32_t b1) {
    asm volatile(
        "mma.sync.aligned.m16n8k16.row.col.f32.bf16.bf16.f32 "
        "{%0,%1,%2,%3}, {%4,%5,%6,%7}, {%8,%9}, {%0,%1,%2,%3};"
        : "+f"(d[0]), "+f"(d[1]), "+f"(d[2]), "+f"(d[3])
        : "r"(a[0]), "r"(a[1]), "r"(a[2]), "r"(a[3]), "r"(b0), "r"(b1));
}

// ---------------- init: zero cnt + dtype detect ----------------
__global__ void k_init(int* cnt, int n, const int* __restrict__ eprobe, int* flag) {
    int i = blockIdx.x * blockDim.x + threadIdx.x;
    if (i < n) cnt[i] = 0;
    if (blockIdx.x == 0) {
        __shared__ int any;
        if (threadIdx.x == 0) any = 0;
        __syncthreads();
        int loc = 0;
        for (int q = threadIdx.x; q < 512; q += blockDim.x)
            if (eprobe[2 * q + 1] != 0) loc = 1;
        if (loc) atomicOr(&any, 1);
        __syncthreads();
        if (threadIdx.x == 0) flag[0] = any ? 0 : 1;
    }
}

__global__ void k_count(const void* __restrict__ ei, int E, int* cnt, const int* flag) {
    int is64 = flag[0];
    int e = blockIdx.x * blockDim.x + threadIdx.x;
    if (e < E) {
        int d = load_idx(ei, (long long)E + e, is64);
        atomicAdd(&cnt[d], 1);
    }
}

__global__ void k_scan1(const int* __restrict__ cnt, int* rowptr, int* bsums, int n) {
    __shared__ int s[1024];
    int i = blockIdx.x * 1024 + threadIdx.x;
    int v = (i < n) ? cnt[i] : 0;
    s[threadIdx.x] = v;
    __syncthreads();
    for (int off = 1; off < 1024; off <<= 1) {
        int t = 0;
        if ((int)threadIdx.x >= off) t = s[threadIdx.x - off];
        __syncthreads();
        s[threadIdx.x] += t;
        __syncthreads();
    }
    if (i < n) rowptr[i] = s[threadIdx.x] - v;
    if (threadIdx.x == 1023) bsums[blockIdx.x] = s[1023];
}

// scan finalize (local bsums scan) + dinv + x prescale + pool zero (fused).
// NOTE: all __syncthreads() are executed by ALL 256 threads (non-divergent).
__global__ void k_scan3(int* rowptr, int* curoff, const int* __restrict__ bsums,
                        const int* __restrict__ cnt, float* dinv,
                        const float* __restrict__ x, float* xs,
                        float* pool, float* gcnt, int n, int E, int nb) {
    __shared__ int pb[128];
    __shared__ int ws[4];
    int t = threadIdx.x;
    int v = 0, orig = 0;
    if (t < 128) {
        v = (t < nb) ? bsums[t] : 0;
        orig = v;
#pragma unroll
        for (int off = 1; off < 32; off <<= 1) {
            int u = __shfl_up_sync(0xffffffffu, v, off);
            if ((t & 31) >= off) v += u;
        }
        if ((t & 31) == 31) ws[t >> 5] = v;
    }
    __syncthreads();
    if (t == 0) { int a = 0; for (int q = 0; q < 4; q++) { int xq = ws[q]; ws[q] = a; a += xq; } }
    __syncthreads();
    if (t < 128) pb[t] = v - orig + ws[t >> 5];   // exclusive prefix
    __syncthreads();

    int i = blockIdx.x * blockDim.x + t;
    if (i < n) {
        int r = rowptr[i] + pb[i >> 10];
        rowptr[i] = r;
        curoff[i] = r;
        float d = rsqrtf((float)cnt[i] + 1.0f);
        dinv[i] = d;
#pragma unroll
        for (int k = 0; k < 5; k++) xs[(size_t)i * 5 + k] = d * x[(size_t)i * 5 + k];
    }
    if (i < NGRAPH * 64) pool[i] = 0.f;
    if (i < NGRAPH) gcnt[i] = 0.f;
    if (i == 0) rowptr[n] = E;
}

__global__ void k_fill(const void* __restrict__ ei, int E,
                       int* curoff, int* col, const int* flag) {
    int is64 = flag[0];
    int e = blockIdx.x * blockDim.x + threadIdx.x;
    if (e >= E) return;
    int s = load_idx(ei, e, is64);
    int d = load_idx(ei, (long long)E + e, is64);
    int p = atomicAdd(&curoff[d], 1);
    col[p] = s;
}

// ---------------- fused layer1: agg(xs) + GEMM(5->64) + relu -> fp16 --------
__global__ void k_l1(const float* __restrict__ xs,
                     const int* __restrict__ rowptr, const int* __restrict__ col,
                     const float* __restrict__ dinv,
                     const float* __restrict__ W1, const float* __restrict__ b1,
                     __half* __restrict__ out, int n) {
    __shared__ float Ws[5 * 64];
    __shared__ float bs[64];
    int t = threadIdx.x;
    for (int i = t; i < 5 * 64; i += 256) Ws[i] = W1[i];
    if (t < 64) bs[t] = b1[t];
    __syncthreads();

    int gt = blockIdx.x * 256 + t;
    int node = gt >> 3;
    int f = gt & 7;
    bool live = (node < n);
    int nodec = live ? node : (n - 1);

    int beg = rowptr[nodec], end = rowptr[nodec + 1];
    bool valid = (f < 5);
    float acc = 0.f;
    int e = beg;
    for (; e + 3 < end; e += 4) {            // MLP=4 on the gather chain
        int s0 = col[e], s1 = col[e + 1], s2 = col[e + 2], s3 = col[e + 3];
        float v0 = 0.f, v1 = 0.f, v2 = 0.f, v3 = 0.f;
        if (valid) {
            v0 = __ldg(&xs[(size_t)s0 * 5 + f]);
            v1 = __ldg(&xs[(size_t)s1 * 5 + f]);
            v2 = __ldg(&xs[(size_t)s2 * 5 + f]);
            v3 = __ldg(&xs[(size_t)s3 * 5 + f]);
        }
        acc += (v0 + v1) + (v2 + v3);
    }
    for (; e < end; e++) {
        int s = col[e];
        if (valid) acc += __ldg(&xs[(size_t)s * 5 + f]);
    }
    float ds = dinv[nodec];
    if (valid) acc = ds * (acc + xs[(size_t)nodec * 5 + f]);

    float v[5];
#pragma unroll
    for (int k = 0; k < 5; k++) v[k] = __shfl_sync(0xffffffffu, acc, k, 8);

    int cb = f * 8;
    float o[8];
#pragma unroll
    for (int j = 0; j < 8; j++) {
        float a = bs[cb + j];
#pragma unroll
        for (int k = 0; k < 5; k++) a += v[k] * Ws[k * 64 + cb + j];
        o[j] = fmaxf(a, 0.f) * ds;
    }
    if (live) {
        __half2 q0 = __float22half2_rn(make_float2(o[0], o[1]));
        __half2 q1 = __float22half2_rn(make_float2(o[2], o[3]));
        __half2 q2 = __float22half2_rn(make_float2(o[4], o[5]));
        __half2 q3 = __float22half2_rn(make_float2(o[6], o[7]));
        uint4 u;
        u.x = *(uint32_t*)&q0; u.y = *(uint32_t*)&q1;
        u.z = *(uint32_t*)&q2; u.w = *(uint32_t*)&q3;
        *reinterpret_cast<uint4*>(&out[(size_t)node * 64 + cb]) = u;
    }
}

// ---------------- fused agg + GEMM2: agg(h1) then (64->128)+b2+relu ---------
__launch_bounds__(256)
__global__ void k_gemm2f(const __half2* __restrict__ h,
                         const int* __restrict__ rowptr, const int* __restrict__ col,
                         const float* __restrict__ dinv,
                         const float* __restrict__ W, const float* __restrict__ bias,
                         float* __restrict__ out, int n) {
    constexpr int K = 64, NC = 128, P = K + 8;
    extern __shared__ char sm[];
    uint16_t* Ah = (uint16_t*)sm;              // [128][P]
    uint16_t* Al = Ah + 128 * P;
    uint16_t* Bh = Al + 128 * P;               // [NC][P]
    uint16_t* Bl = Bh + NC * P;

    const int tid = threadIdx.x;
    const int wid = tid >> 5;
    const int lane = tid & 31;
    const int nodeBase = blockIdx.x * 128;

    // B conversion: W[K][NC] -> Bsm[n][k] bf16 hi/lo
    for (int q = tid; q < NC * (K / 2); q += 256) {
        int nrow = q % NC;
        int k2 = (q / NC) * 2;
        float a = __ldg(&W[(size_t)k2 * NC + nrow]);
        float b = __ldg(&W[(size_t)(k2 + 1) * NC + nrow]);
        uint32_t hh, ll;
        split2(a, b, hh, ll);
        *(uint32_t*)&Bh[nrow * P + k2] = hh;
        *(uint32_t*)&Bl[nrow * P + k2] = ll;
    }

    // A: aggregate 16 rows per warp from h1, split to bf16 hi/lo in smem
    for (int rr = 0; rr < 16; rr++) {
        int r = wid * 16 + rr;
        int gn = nodeBase + r;
        float a0 = 0.f, a1 = 0.f;
        if (gn < n) {
            int beg = rowptr[gn], end = rowptr[gn + 1];
            int e = beg;
            for (; e + 3 < end; e += 4) {
                int s0 = col[e], s1 = col[e + 1], s2 = col[e + 2], s3 = col[e + 3];
                float2 f0 = __half22float2(__ldg(&h[(size_t)s0 * 32 + lane]));
                float2 f1 = __half22float2(__ldg(&h[(size_t)s1 * 32 + lane]));
                float2 f2 = __half22float2(__ldg(&h[(size_t)s2 * 32 + lane]));
                float2 f3 = __half22float2(__ldg(&h[(size_t)s3 * 32 + lane]));
                a0 += (f0.x + f1.x) + (f2.x + f3.x);
                a1 += (f0.y + f1.y) + (f2.y + f3.y);
            }
            for (; e < end; e++) {
                int s = col[e];
                float2 f = __half22float2(__ldg(&h[(size_t)s * 32 + lane]));
                a0 += f.x;
                a1 += f.y;
            }
            float2 self = __half22float2(__ldg(&h[(size_t)gn * 32 + lane]));
            float ds = dinv[gn];
            a0 = ds * (a0 + self.x);
            a1 = ds * (a1 + self.y);
        }
        uint32_t hh, ll;
        split2(a0, a1, hh, ll);
        *(uint32_t*)&Ah[r * P + 2 * lane] = hh;
        *(uint32_t*)&Al[r * P + 2 * lane] = ll;
    }
    __syncthreads();

    const int g = lane >> 2;
    const int t4 = lane & 3;
    const int warpRow = wid * 16;

    float acc[NC / 8][4];
#pragma unroll
    for (int nt = 0; nt < NC / 8; nt++)
#pragma unroll
        for (int j = 0; j < 4; j++) acc[nt][j] = 0.f;

#pragma unroll
    for (int ks = 0; ks < K / 16; ks++) {
        int k0 = ks * 16;
        int r0 = warpRow + g;
        uint32_t ah[4], al[4];
        ah[0] = *(uint32_t*)&Ah[r0 * P + k0 + 2 * t4];
        ah[1] = *(uint32_t*)&Ah[(r0 + 8) * P + k0 + 2 * t4];
        ah[2] = *(uint32_t*)&Ah[r0 * P + k0 + 2 * t4 + 8];
        ah[3] = *(uint32_t*)&Ah[(r0 + 8) * P + k0 + 2 * t4 + 8];
        al[0] = *(uint32_t*)&Al[r0 * P + k0 + 2 * t4];
        al[1] = *(uint32_t*)&Al[(r0 + 8) * P + k0 + 2 * t4];
        al[2] = *(uint32_t*)&Al[r0 * P + k0 + 2 * t4 + 8];
        al[3] = *(uint32_t*)&Al[(r0 + 8) * P + k0 + 2 * t4 + 8];
#pragma unroll
        for (int nt = 0; nt < NC / 8; nt++) {
            int nr = nt * 8 + g;
            uint32_t bh0 = *(uint32_t*)&Bh[nr * P + k0 + 2 * t4];
            uint32_t bh1 = *(uint32_t*)&Bh[nr * P + k0 + 2 * t4 + 8];
            uint32_t bl0 = *(uint32_t*)&Bl[nr * P + k0 + 2 * t4];
            uint32_t bl1 = *(uint32_t*)&Bl[nr * P + k0 + 2 * t4 + 8];
            mma16816(acc[nt], ah, bh0, bh1);
            mma16816(acc[nt], ah, bl0, bl1);
            mma16816(acc[nt], al, bh0, bh1);
        }
    }

    int row0 = nodeBase + warpRow + g;
    int row1 = row0 + 8;
    bool l0 = row0 < n, l1 = row1 < n;
#pragma unroll
    for (int nt = 0; nt < NC / 8; nt++) {
        int colc = nt * 8 + 2 * t4;
        float b0 = __ldg(&bias[colc]);
        float b1 = __ldg(&bias[colc + 1]);
        float v0 = fmaxf(acc[nt][0] + b0, 0.f);
        float v1 = fmaxf(acc[nt][1] + b1, 0.f);
        float v2 = fmaxf(acc[nt][2] + b0, 0.f);
        float v3 = fmaxf(acc[nt][3] + b1, 0.f);
        if (l0) *reinterpret_cast<float2*>(&out[(size_t)row0 * NC + colc]) = make_float2(v0, v1);
        if (l1) *reinterpret_cast<float2*>(&out[(size_t)row1 * NC + colc]) = make_float2(v2, v3);
    }
}

// ---------------- mma GEMM3: (128->64), *dinv, fp16 out ----------------
__launch_bounds__(256)
__global__ void k_gemm3(const float* __restrict__ A, const float* __restrict__ W,
                        const float* __restrict__ dinv, __half* __restrict__ out, int n) {
    constexpr int K = 128, NC = 64, P = K + 8;
    extern __shared__ char sm[];
    uint16_t* Ah = (uint16_t*)sm;
    uint16_t* Al = Ah + 128 * P;
    uint16_t* Bh = Al + 128 * P;
    uint16_t* Bl = Bh + NC * P;

    const int tid = threadIdx.x;
    const int nodeBase = blockIdx.x * 128;

    for (int q = tid; q < 128 * (K / 2); q += 256) {
        int r = q / (K / 2);
        int c2 = (q % (K / 2)) * 2;
        int gn = nodeBase + r;
        float2 v = (gn < n) ? *reinterpret_cast<const float2*>(&A[(size_t)gn * K + c2])
                            : make_float2(0.f, 0.f);
        uint32_t h, l;
        split2(v.x, v.y, h, l);
        *(uint32_t*)&Ah[r * P + c2] = h;
        *(uint32_t*)&Al[r * P + c2] = l;
    }
    for (int q = tid; q < NC * (K / 2); q += 256) {
        int nrow = q % NC;
        int k2 = (q / NC) * 2;
        float a = __ldg(&W[(size_t)k2 * NC + nrow]);
        float b = __ldg(&W[(size_t)(k2 + 1) * NC + nrow]);
        uint32_t h, l;
        split2(a, b, h, l);
        *(uint32_t*)&Bh[nrow * P + k2] = h;
        *(uint32_t*)&Bl[nrow * P + k2] = l;
    }
    __syncthreads();

    const int wid = tid >> 5;
    const int lane = tid & 31;
    const int g = lane >> 2;
    const int t4 = lane & 3;
    const int warpRow = wid * 16;

    float acc[NC / 8][4];
#pragma unroll
    for (int nt = 0; nt < NC / 8; nt++)
#pragma unroll
        for (int j = 0; j < 4; j++) acc[nt][j] = 0.f;

#pragma unroll
    for (int ks = 0; ks < K / 16; ks++) {
        int k0 = ks * 16;
        int r0 = warpRow + g;
        uint32_t ah[4], al[4];
        ah[0] = *(uint32_t*)&Ah[r0 * P + k0 + 2 * t4];
        ah[1] = *(uint32_t*)&Ah[(r0 + 8) * P + k0 + 2 * t4];
        ah[2] = *(uint32_t*)&Ah[r0 * P + k0 + 2 * t4 + 8];
        ah[3] = *(uint32_t*)&Ah[(r0 + 8) * P + k0 + 2 * t4 + 8];
        al[0] = *(uint32_t*)&Al[r0 * P + k0 + 2 * t4];
        al[1] = *(uint32_t*)&Al[(r0 + 8) * P + k0 + 2 * t4];
        al[2] = *(uint32_t*)&Al[r0 * P + k0 + 2 * t4 + 8];
        al[3] = *(uint32_t*)&Al[(r0 + 8) * P + k0 + 2 * t4 + 8];
#pragma unroll
        for (int nt = 0; nt < NC / 8; nt++) {
            int nr = nt * 8 + g;
            uint32_t bh0 = *(uint32_t*)&Bh[nr * P + k0 + 2 * t4];
            uint32_t bh1 = *(uint32_t*)&Bh[nr * P + k0 + 2 * t4 + 8];
            uint32_t bl0 = *(uint32_t*)&Bl[nr * P + k0 + 2 * t4];
            uint32_t bl1 = *(uint32_t*)&Bl[nr * P + k0 + 2 * t4 + 8];
            mma16816(acc[nt], ah, bh0, bh1);
            mma16816(acc[nt], ah, bl0, bl1);
            mma16816(acc[nt], al, bh0, bh1);
        }
    }

    int row0 = nodeBase + warpRow + g;
    int row1 = row0 + 8;
    bool l0 = row0 < n, l1 = row1 < n;
    float ds0 = l0 ? dinv[row0] : 1.0f;
    float ds1 = l1 ? dinv[row1] : 1.0f;
#pragma unroll
    for (int nt = 0; nt < NC / 8; nt++) {
        int colc = nt * 8 + 2 * t4;
        if (l0) {
            __half2 hh = __float22half2_rn(make_float2(acc[nt][0] * ds0, acc[nt][1] * ds0));
            *(uint32_t*)&out[(size_t)row0 * NC + colc] = *(uint32_t*)&hh;
        }
        if (l1) {
            __half2 hh = __float22half2_rn(make_float2(acc[nt][2] * ds1, acc[nt][3] * ds1));
            *(uint32_t*)&out[(size_t)row1 * NC + colc] = *(uint32_t*)&hh;
        }
    }
}

// ---------------- agg width 64 on fp16 + bias + relu + mean-pool ----------
__global__ void k_aggpool(const __half2* __restrict__ h,
                          const int* __restrict__ rowptr, const int* __restrict__ col,
                          const float* __restrict__ dinv,
                          const float* __restrict__ bias,
                          const void* __restrict__ batch, const int* flag,
                          float* pool, float* gcnt, int n) {
    int node = blockIdx.x * 8 + (threadIdx.x >> 5);
    int lane = threadIdx.x & 31;
    if (node >= n) return;
    int beg = rowptr[node], end = rowptr[node + 1];
    float a0 = 0.f, a1 = 0.f;
    int e = beg;
    for (; e + 3 < end; e += 4) {
        int s0 = col[e], s1 = col[e + 1], s2 = col[e + 2], s3 = col[e + 3];
        float2 f0 = __half22float2(__ldg(&h[(size_t)s0 * 32 + lane]));
        float2 f1 = __half22float2(__ldg(&h[(size_t)s1 * 32 + lane]));
        float2 f2 = __half22float2(__ldg(&h[(size_t)s2 * 32 + lane]));
        float2 f3 = __half22float2(__ldg(&h[(size_t)s3 * 32 + lane]));
        a0 += (f0.x + f1.x) + (f2.x + f3.x);
        a1 += (f0.y + f1.y) + (f2.y + f3.y);
    }
    for (; e < end; e++) {
        int s = col[e];
        float2 f = __half22float2(__ldg(&h[(size_t)s * 32 + lane]));
        a0 += f.x;
        a1 += f.y;
    }
    float2 self = __half22float2(h[(size_t)node * 32 + lane]);
    float ds = dinv[node];
    a0 = fmaxf(ds * (a0 + self.x) + __ldg(&bias[2 * lane]), 0.f);
    a1 = fmaxf(ds * (a1 + self.y) + __ldg(&bias[2 * lane + 1]), 0.f);
    int g = load_idx(batch, node, flag[0]);
    atomicAdd(&pool[g * 64 + 2 * lane], a0);
    atomicAdd(&pool[g * 64 + 2 * lane + 1], a1);
    if (lane == 0) atomicAdd(&gcnt[g], 1.0f);
}

// ---------------- final FC + sigmoid ----------------
__global__ void k_final(const float* __restrict__ pool, const float* __restrict__ gcnt,
                        const float* __restrict__ Wfc, const float* __restrict__ bfc,
                        float* __restrict__ out) {
    int g = threadIdx.x;
    float c = fmaxf(gcnt[g], 1.0f);
    float acc = 0.f;
#pragma unroll
    for (int k = 0; k < 64; k++) acc += pool[g * 64 + k] * Wfc[k];
    acc = acc / c + bfc[0];
    out[g] = 1.f / (1.f + expf(-acc));
}

// ---------------- launch ----------------
extern "C" void kernel_launch(void* const* d_in, const int* in_sizes, int n_in,
                              void* d_out, int out_size) {
    const float*  x     = (const float*)d_in[0];
    const void*   ei    = d_in[1];
    const void*   batch = d_in[2];
    const float*  W1    = (const float*)d_in[3];
    const float*  b1    = (const float*)d_in[4];
    const float*  W2    = (const float*)d_in[5];
    const float*  b2    = (const float*)d_in[6];
    const float*  W3    = (const float*)d_in[7];
    const float*  b3    = (const float*)d_in[8];
    const float*  Wfc   = (const float*)d_in[9];
    const float*  bfc   = (const float*)d_in[10];
    float*        out   = (float*)d_out;

    const int N = in_sizes[0] / 5;
    const int E = in_sizes[1] / 2;

    float *bufA, *xs, *dinv, *pool, *gcnt;
    __half *h1, *h3;
    int *cnt, *rowptr, *curoff, *col, *bsums, *is64;
    cudaGetSymbolAddress((void**)&bufA, g_bufA);
    cudaGetSymbolAddress((void**)&h1, g_h1);
    cudaGetSymbolAddress((void**)&h3, g_h3);
    cudaGetSymbolAddress((void**)&xs, g_xs);
    cudaGetSymbolAddress((void**)&dinv, g_dinv);
    cudaGetSymbolAddress((void**)&pool, g_pool);
    cudaGetSymbolAddress((void**)&gcnt, g_gcnt);
    cudaGetSymbolAddress((void**)&cnt, g_cnt);
    cudaGetSymbolAddress((void**)&rowptr, g_rowptr);
    cudaGetSymbolAddress((void**)&curoff, g_curoff);
    cudaGetSymbolAddress((void**)&col, g_col);
    cudaGetSymbolAddress((void**)&bsums, g_bsums);
    cudaGetSymbolAddress((void**)&is64, g_is64);

    const int SM2 = (128 + 128) * (64 + 8) * 2 * 2;
    const int SM3 = (128 + 64) * (128 + 8) * 2 * 2;
    static int smem_set = 0;
    if (!smem_set) {
        cudaFuncSetAttribute(k_gemm2f, cudaFuncAttributeMaxDynamicSharedMemorySize, SM2);
        cudaFuncSetAttribute(k_gemm3, cudaFuncAttributeMaxDynamicSharedMemorySize, SM3);
        smem_set = 1;
    }

    const int TB = 256;
    k_init<<<(N + TB - 1) / TB, TB>>>(cnt, N, (const int*)ei, is64);
    k_count<<<(E + TB - 1) / TB, TB>>>(ei, E, cnt, is64);

    int nb = (N + 1023) / 1024;
    k_scan1<<<nb, 1024>>>(cnt, rowptr, bsums, N);
    k_scan3<<<(N + TB - 1) / TB, TB>>>(rowptr, curoff, bsums, cnt, dinv, x, xs,
                                       pool, gcnt, N, E, nb);
    k_fill<<<(E + TB - 1) / TB, TB>>>(ei, E, curoff, col, is64);

    // L1 fused: agg5 + GEMM(5->64) + relu, prescaled -> h1 (fp16)
    k_l1<<<(N * 8 + TB - 1) / TB, TB>>>(xs, rowptr, col, dinv, W1, b1, h1, N);

    // L2: fused agg(h1) + mma GEMM(64->128)+b2+relu -> bufA (fp32)
    int gtc = (N + 127) / 128;
    k_gemm2f<<<gtc, 256, SM2>>>((const __half2*)h1, rowptr, col, dinv, W2, b2, bufA, N);

    // L3: mma GEMM(128->64) *dinv -> h3 (fp16); agg + b3 + relu + pool
    k_gemm3<<<gtc, 256, SM3>>>(bufA, W3, dinv, h3, N);
    k_aggpool<<<(N + 7) / 8, TB>>>((const __half2*)h3, rowptr, col, dinv, b3,
                                   batch, is64, pool, gcnt, N);

    k_final<<<1, NGRAPH>>>(pool, gcnt, Wfc, bfc, out);
}

// round 12
// speedup vs baseline: 1.0952x; 1.0952x over previous
#include <cuda_runtime.h>
#include <cuda_bf16.h>
#include <cuda_fp16.h>
#include <math.h>
#include <stdint.h>

// ---------------- static scratch (no allocations allowed) ----------------
#define MAXN 100000
#define MAXE 1600000
#define NGRAPH 256

__device__ float  g_bufA[(size_t)MAXN * 128];   // fp32 (N x 128)
__device__ float  g_bufB[(size_t)MAXN * 64];    // fp32 (N x 64)
__device__ __half g_h1[(size_t)MAXN * 64];      // fp16 gather array (layer1 out)
__device__ __half g_h3[(size_t)MAXN * 64];      // fp16 gather array (gemm3 out)
__device__ float  g_xs[(size_t)MAXN * 5];
__device__ int    g_cnt[MAXN];
__device__ int    g_rowptr[MAXN + 1];
__device__ int    g_curoff[MAXN];
__device__ float  g_dinv[MAXN];
__device__ int    g_col[MAXE];
__device__ int    g_bsums[128];
__device__ float  g_pool[NGRAPH * 64];
__device__ float  g_gcnt[NGRAPH];
__device__ int    g_is64[1];

__device__ __forceinline__ int load_idx(const void* p, long long i, int is64) {
    if (is64) return (int)((const long long*)p)[i];
    return ((const int*)p)[i];
}

__device__ __forceinline__ void split2(float a, float b, uint32_t& hi, uint32_t& lo) {
    __nv_bfloat16 ah = __float2bfloat16(a);
    __nv_bfloat16 bh = __float2bfloat16(b);
    __nv_bfloat16 al = __float2bfloat16(a - __bfloat162float(ah));
    __nv_bfloat16 bl = __float2bfloat16(b - __bfloat162float(bh));
    unsigned short ahu = *(unsigned short*)&ah, bhu = *(unsigned short*)&bh;
    unsigned short alu = *(unsigned short*)&al, blu = *(unsigned short*)&bl;
    hi = ((uint32_t)bhu << 16) | ahu;
    lo = ((uint32_t)blu << 16) | alu;
}

__device__ __forceinline__ void mma16816(float* d, const uint32_t* a,
                                         uint32_t b0, uint32_t b1) {
    asm volatile(
        "mma.sync.aligned.m16n8k16.row.col.f32.bf16.bf16.f32 "
        "{%0,%1,%2,%3}, {%4,%5,%6,%7}, {%8,%9}, {%0,%1,%2,%3};"
        : "+f"(d[0]), "+f"(d[1]), "+f"(d[2]), "+f"(d[3])
        : "r"(a[0]), "r"(a[1]), "r"(a[2]), "r"(a[3]), "r"(b0), "r"(b1));
}

// ---------------- init: zero cnt + dtype detect ----------------
__global__ void k_init(int* cnt, int n, const int* __restrict__ eprobe, int* flag) {
    int i = blockIdx.x * blockDim.x + threadIdx.x;
    if (i < n) cnt[i] = 0;
    if (blockIdx.x == 0) {
        __shared__ int any;
        if (threadIdx.x == 0) any = 0;
        __syncthreads();
        int loc = 0;
        for (int q = threadIdx.x; q < 512; q += blockDim.x)
            if (eprobe[2 * q + 1] != 0) loc = 1;
        if (loc) atomicOr(&any, 1);
        __syncthreads();
        if (threadIdx.x == 0) flag[0] = any ? 0 : 1;
    }
}

__global__ void k_count(const void* __restrict__ ei, int E, int* cnt, const int* flag) {
    int is64 = flag[0];
    int e = blockIdx.x * blockDim.x + threadIdx.x;
    if (e < E) {
        int d = load_idx(ei, (long long)E + e, is64);
        atomicAdd(&cnt[d], 1);
    }
}

__global__ void k_scan1(const int* __restrict__ cnt, int* rowptr, int* bsums, int n) {
    __shared__ int s[1024];
    int i = blockIdx.x * 1024 + threadIdx.x;
    int v = (i < n) ? cnt[i] : 0;
    s[threadIdx.x] = v;
    __syncthreads();
    for (int off = 1; off < 1024; off <<= 1) {
        int t = 0;
        if ((int)threadIdx.x >= off) t = s[threadIdx.x - off];
        __syncthreads();
        s[threadIdx.x] += t;
        __syncthreads();
    }
    if (i < n) rowptr[i] = s[threadIdx.x] - v;
    if (threadIdx.x == 1023) bsums[blockIdx.x] = s[1023];
}

// scan finalize (local bsums scan) + dinv + x prescale + pool zero (fused).
// All __syncthreads() executed by all 256 threads (non-divergent).
__global__ void k_scan3(int* rowptr, int* curoff, const int* __restrict__ bsums,
                        const int* __restrict__ cnt, float* dinv,
                        const float* __restrict__ x, float* xs,
                        float* pool, float* gcnt, int n, int E, int nb) {
    __shared__ int pb[128];
    __shared__ int ws[4];
    int t = threadIdx.x;
    int v = 0, orig = 0;
    if (t < 128) {
        v = (t < nb) ? bsums[t] : 0;
        orig = v;
#pragma unroll
        for (int off = 1; off < 32; off <<= 1) {
            int u = __shfl_up_sync(0xffffffffu, v, off);
            if ((t & 31) >= off) v += u;
        }
        if ((t & 31) == 31) ws[t >> 5] = v;
    }
    __syncthreads();
    if (t == 0) { int a = 0; for (int q = 0; q < 4; q++) { int xq = ws[q]; ws[q] = a; a += xq; } }
    __syncthreads();
    if (t < 128) pb[t] = v - orig + ws[t >> 5];
    __syncthreads();

    int i = blockIdx.x * blockDim.x + t;
    if (i < n) {
        int r = rowptr[i] + pb[i >> 10];
        rowptr[i] = r;
        curoff[i] = r;
        float d = rsqrtf((float)cnt[i] + 1.0f);
        dinv[i] = d;
#pragma unroll
        for (int k = 0; k < 5; k++) xs[(size_t)i * 5 + k] = d * x[(size_t)i * 5 + k];
    }
    if (i < NGRAPH * 64) pool[i] = 0.f;
    if (i < NGRAPH) gcnt[i] = 0.f;
    if (i == 0) rowptr[n] = E;
}

__global__ void k_fill(const void* __restrict__ ei, int E,
                       int* curoff, int* col, const int* flag) {
    int is64 = flag[0];
    int e = blockIdx.x * blockDim.x + threadIdx.x;
    if (e >= E) return;
    int s = load_idx(ei, e, is64);
    int d = load_idx(ei, (long long)E + e, is64);
    int p = atomicAdd(&curoff[d], 1);
    col[p] = s;
}

// ---------------- fused layer1: agg(xs) + GEMM(5->64) + relu -> fp16 --------
__global__ void k_l1(const float* __restrict__ xs,
                     const int* __restrict__ rowptr, const int* __restrict__ col,
                     const float* __restrict__ dinv,
                     const float* __restrict__ W1, const float* __restrict__ b1,
                     __half* __restrict__ out, int n) {
    __shared__ float Ws[5 * 64];
    __shared__ float bs[64];
    int t = threadIdx.x;
    for (int i = t; i < 5 * 64; i += 256) Ws[i] = W1[i];
    if (t < 64) bs[t] = b1[t];
    __syncthreads();

    int gt = blockIdx.x * 256 + t;
    int node = gt >> 3;
    int f = gt & 7;
    bool live = (node < n);
    int nodec = live ? node : (n - 1);

    int beg = rowptr[nodec], end = rowptr[nodec + 1];
    bool valid = (f < 5);
    float acc = 0.f;
    int e = beg;
    for (; e + 3 < end; e += 4) {
        int s0 = col[e], s1 = col[e + 1], s2 = col[e + 2], s3 = col[e + 3];
        float v0 = 0.f, v1 = 0.f, v2 = 0.f, v3 = 0.f;
        if (valid) {
            v0 = __ldg(&xs[(size_t)s0 * 5 + f]);
            v1 = __ldg(&xs[(size_t)s1 * 5 + f]);
            v2 = __ldg(&xs[(size_t)s2 * 5 + f]);
            v3 = __ldg(&xs[(size_t)s3 * 5 + f]);
        }
        acc += (v0 + v1) + (v2 + v3);
    }
    for (; e < end; e++) {
        int s = col[e];
        if (valid) acc += __ldg(&xs[(size_t)s * 5 + f]);
    }
    float ds = dinv[nodec];
    if (valid) acc = ds * (acc + xs[(size_t)nodec * 5 + f]);

    float v[5];
#pragma unroll
    for (int k = 0; k < 5; k++) v[k] = __shfl_sync(0xffffffffu, acc, k, 8);

    int cb = f * 8;
    float o[8];
#pragma unroll
    for (int j = 0; j < 8; j++) {
        float a = bs[cb + j];
#pragma unroll
        for (int k = 0; k < 5; k++) a += v[k] * Ws[k * 64 + cb + j];
        o[j] = fmaxf(a, 0.f) * ds;
    }
    if (live) {
        __half2 q0 = __float22half2_rn(make_float2(o[0], o[1]));
        __half2 q1 = __float22half2_rn(make_float2(o[2], o[3]));
        __half2 q2 = __float22half2_rn(make_float2(o[4], o[5]));
        __half2 q3 = __float22half2_rn(make_float2(o[6], o[7]));
        uint4 u;
        u.x = *(uint32_t*)&q0; u.y = *(uint32_t*)&q1;
        u.z = *(uint32_t*)&q2; u.w = *(uint32_t*)&q3;
        *reinterpret_cast<uint4*>(&out[(size_t)node * 64 + cb]) = u;
    }
}

// ---------------- agg width 64 on fp16: warp/node, half2 loads, 4x unroll ----
template <bool POOL>
__global__ void k_agg64h(const __half2* __restrict__ h,
                         const int* __restrict__ rowptr, const int* __restrict__ col,
                         const float* __restrict__ dinv,
                         const float* __restrict__ bias,
                         const void* __restrict__ batch, const int* flag,
                         float* __restrict__ out, float* pool, float* gcnt, int n) {
    int node = blockIdx.x * 8 + (threadIdx.x >> 5);
    int lane = threadIdx.x & 31;
    if (node >= n) return;
    int beg = rowptr[node], end = rowptr[node + 1];
    float a0 = 0.f, a1 = 0.f;
    int e = beg;
    for (; e + 3 < end; e += 4) {
        int s0 = col[e], s1 = col[e + 1], s2 = col[e + 2], s3 = col[e + 3];
        float2 f0 = __half22float2(__ldg(&h[(size_t)s0 * 32 + lane]));
        float2 f1 = __half22float2(__ldg(&h[(size_t)s1 * 32 + lane]));
        float2 f2 = __half22float2(__ldg(&h[(size_t)s2 * 32 + lane]));
        float2 f3 = __half22float2(__ldg(&h[(size_t)s3 * 32 + lane]));
        a0 += (f0.x + f1.x) + (f2.x + f3.x);
        a1 += (f0.y + f1.y) + (f2.y + f3.y);
    }
    for (; e < end; e++) {
        int s = col[e];
        float2 f = __half22float2(__ldg(&h[(size_t)s * 32 + lane]));
        a0 += f.x;
        a1 += f.y;
    }
    float2 self = __half22float2(h[(size_t)node * 32 + lane]);
    float ds = dinv[node];
    a0 = ds * (a0 + self.x);
    a1 = ds * (a1 + self.y);
    if (POOL) {
        a0 = fmaxf(a0 + __ldg(&bias[2 * lane]), 0.f);
        a1 = fmaxf(a1 + __ldg(&bias[2 * lane + 1]), 0.f);
        int g = load_idx(batch, node, flag[0]);
        atomicAdd(&pool[g * 64 + 2 * lane], a0);
        atomicAdd(&pool[g * 64 + 2 * lane + 1], a1);
        if (lane == 0) atomicAdd(&gcnt[g], 1.0f);
    } else {
        *reinterpret_cast<float2*>(&out[(size_t)node * 64 + 2 * lane]) =
            make_float2(a0, a1);
    }
}

// ---------------- mma.sync bf16 split GEMM: 128-row tile, 8 warps ----------
template <int K, int NC, bool RELU, bool SCALE, bool HALFOUT>
__launch_bounds__(256)
__global__ void k_gemm_mma(const float* __restrict__ A, const float* __restrict__ W,
                           const float* __restrict__ bias, const float* __restrict__ dinv,
                           void* __restrict__ outv, int n) {
    constexpr int P = K + 8;
    extern __shared__ char sm[];
    uint16_t* Ah = (uint16_t*)sm;
    uint16_t* Al = Ah + 128 * P;
    uint16_t* Bh = Al + 128 * P;
    uint16_t* Bl = Bh + NC * P;

    const int tid = threadIdx.x;
    const int nodeBase = blockIdx.x * 128;

    for (int q = tid; q < 128 * (K / 2); q += 256) {
        int r = q / (K / 2);
        int c2 = (q % (K / 2)) * 2;
        int gn = nodeBase + r;
        float2 v = (gn < n) ? *reinterpret_cast<const float2*>(&A[(size_t)gn * K + c2])
                            : make_float2(0.f, 0.f);
        uint32_t h, l;
        split2(v.x, v.y, h, l);
        *(uint32_t*)&Ah[r * P + c2] = h;
        *(uint32_t*)&Al[r * P + c2] = l;
    }
    for (int q = tid; q < NC * (K / 2); q += 256) {
        int nrow = q % NC;
        int k2 = (q / NC) * 2;
        float a = __ldg(&W[(size_t)k2 * NC + nrow]);
        float b = __ldg(&W[(size_t)(k2 + 1) * NC + nrow]);
        uint32_t h, l;
        split2(a, b, h, l);
        *(uint32_t*)&Bh[nrow * P + k2] = h;
        *(uint32_t*)&Bl[nrow * P + k2] = l;
    }
    __syncthreads();

    const int wid = tid >> 5;
    const int lane = tid & 31;
    const int g = lane >> 2;
    const int t4 = lane & 3;
    const int warpRow = wid * 16;

    float acc[NC / 8][4];
#pragma unroll
    for (int nt = 0; nt < NC / 8; nt++)
#pragma unroll
        for (int j = 0; j < 4; j++) acc[nt][j] = 0.f;

#pragma unroll
    for (int ks = 0; ks < K / 16; ks++) {
        int k0 = ks * 16;
        int r0 = warpRow + g;
        uint32_t ah[4], al[4];
        ah[0] = *(uint32_t*)&Ah[r0 * P + k0 + 2 * t4];
        ah[1] = *(uint32_t*)&Ah[(r0 + 8) * P + k0 + 2 * t4];
        ah[2] = *(uint32_t*)&Ah[r0 * P + k0 + 2 * t4 + 8];
        ah[3] = *(uint32_t*)&Ah[(r0 + 8) * P + k0 + 2 * t4 + 8];
        al[0] = *(uint32_t*)&Al[r0 * P + k0 + 2 * t4];
        al[1] = *(uint32_t*)&Al[(r0 + 8) * P + k0 + 2 * t4];
        al[2] = *(uint32_t*)&Al[r0 * P + k0 + 2 * t4 + 8];
        al[3] = *(uint32_t*)&Al[(r0 + 8) * P + k0 + 2 * t4 + 8];
#pragma unroll
        for (int nt = 0; nt < NC / 8; nt++) {
            int nr = nt * 8 + g;
            uint32_t bh0 = *(uint32_t*)&Bh[nr * P + k0 + 2 * t4];
            uint32_t bh1 = *(uint32_t*)&Bh[nr * P + k0 + 2 * t4 + 8];
            uint32_t bl0 = *(uint32_t*)&Bl[nr * P + k0 + 2 * t4];
            uint32_t bl1 = *(uint32_t*)&Bl[nr * P + k0 + 2 * t4 + 8];
            mma16816(acc[nt], ah, bh0, bh1);
            mma16816(acc[nt], ah, bl0, bl1);
            mma16816(acc[nt], al, bh0, bh1);
        }
    }

    int row0 = nodeBase + warpRow + g;
    int row1 = row0 + 8;
    bool l0 = row0 < n, l1 = row1 < n;
    float ds0 = (SCALE && l0) ? dinv[row0] : 1.0f;
    float ds1 = (SCALE && l1) ? dinv[row1] : 1.0f;
#pragma unroll
    for (int nt = 0; nt < NC / 8; nt++) {
        int colc = nt * 8 + 2 * t4;
        float b0 = RELU ? __ldg(&bias[colc]) : 0.f;
        float b1 = RELU ? __ldg(&bias[colc + 1]) : 0.f;
        float v0 = acc[nt][0], v1 = acc[nt][1], v2 = acc[nt][2], v3 = acc[nt][3];
        if (RELU) {
            v0 = fmaxf(v0 + b0, 0.f); v1 = fmaxf(v1 + b1, 0.f);
            v2 = fmaxf(v2 + b0, 0.f); v3 = fmaxf(v3 + b1, 0.f);
        }
        if (SCALE) { v0 *= ds0; v1 *= ds0; v2 *= ds1; v3 *= ds1; }
        if (HALFOUT) {
            __half* out = (__half*)outv;
            if (l0) {
                __half2 hh = __float22half2_rn(make_float2(v0, v1));
                *(uint32_t*)&out[(size_t)row0 * NC + colc] = *(uint32_t*)&hh;
            }
            if (l1) {
                __half2 hh = __float22half2_rn(make_float2(v2, v3));
                *(uint32_t*)&out[(size_t)row1 * NC + colc] = *(uint32_t*)&hh;
            }
        } else {
            float* out = (float*)outv;
            if (l0) *reinterpret_cast<float2*>(&out[(size_t)row0 * NC + colc]) = make_float2(v0, v1);
            if (l1) *reinterpret_cast<float2*>(&out[(size_t)row1 * NC + colc]) = make_float2(v2, v3);
        }
    }
}

// ---------------- final FC + sigmoid ----------------
__global__ void k_final(const float* __restrict__ pool, const float* __restrict__ gcnt,
                        const float* __restrict__ Wfc, const float* __restrict__ bfc,
                        float* __restrict__ out) {
    int g = threadIdx.x;
    float c = fmaxf(gcnt[g], 1.0f);
    float acc = 0.f;
#pragma unroll
    for (int k = 0; k < 64; k++) acc += pool[g * 64 + k] * Wfc[k];
    acc = acc / c + bfc[0];
    out[g] = 1.f / (1.f + expf(-acc));
}

// ---------------- launch ----------------
extern "C" void kernel_launch(void* const* d_in, const int* in_sizes, int n_in,
                              void* d_out, int out_size) {
    const float*  x     = (const float*)d_in[0];
    const void*   ei    = d_in[1];
    const void*   batch = d_in[2];
    const float*  W1    = (const float*)d_in[3];
    const float*  b1    = (const float*)d_in[4];
    const float*  W2    = (const float*)d_in[5];
    const float*  b2    = (const float*)d_in[6];
    const float*  W3    = (const float*)d_in[7];
    const float*  b3    = (const float*)d_in[8];
    const float*  Wfc   = (const float*)d_in[9];
    const float*  bfc   = (const float*)d_in[10];
    float*        out   = (float*)d_out;

    const int N = in_sizes[0] / 5;
    const int E = in_sizes[1] / 2;

    float *bufA, *bufB, *xs, *dinv, *pool, *gcnt;
    __half *h1, *h3;
    int *cnt, *rowptr, *curoff, *col, *bsums, *is64;
    cudaGetSymbolAddress((void**)&bufA, g_bufA);
    cudaGetSymbolAddress((void**)&bufB, g_bufB);
    cudaGetSymbolAddress((void**)&h1, g_h1);
    cudaGetSymbolAddress((void**)&h3, g_h3);
    cudaGetSymbolAddress((void**)&xs, g_xs);
    cudaGetSymbolAddress((void**)&dinv, g_dinv);
    cudaGetSymbolAddress((void**)&pool, g_pool);
    cudaGetSymbolAddress((void**)&gcnt, g_gcnt);
    cudaGetSymbolAddress((void**)&cnt, g_cnt);
    cudaGetSymbolAddress((void**)&rowptr, g_rowptr);
    cudaGetSymbolAddress((void**)&curoff, g_curoff);
    cudaGetSymbolAddress((void**)&col, g_col);
    cudaGetSymbolAddress((void**)&bsums, g_bsums);
    cudaGetSymbolAddress((void**)&is64, g_is64);

    const int SM2 = (128 + 128) * (64 + 8) * 2 * 2;
    const int SM3 = (128 + 64) * (128 + 8) * 2 * 2;
    static int smem_set = 0;
    if (!smem_set) {
        cudaFuncSetAttribute(k_gemm_mma<64, 128, true, false, false>,
                             cudaFuncAttributeMaxDynamicSharedMemorySize, SM2);
        cudaFuncSetAttribute(k_gemm_mma<128, 64, false, true, true>,
                             cudaFuncAttributeMaxDynamicSharedMemorySize, SM3);
        smem_set = 1;
    }

    const int TB = 256;
    k_init<<<(N + TB - 1) / TB, TB>>>(cnt, N, (const int*)ei, is64);
    k_count<<<(E + TB - 1) / TB, TB>>>(ei, E, cnt, is64);

    int nb = (N + 1023) / 1024;
    k_scan1<<<nb, 1024>>>(cnt, rowptr, bsums, N);
    k_scan3<<<(N + TB - 1) / TB, TB>>>(rowptr, curoff, bsums, cnt, dinv, x, xs,
                                       pool, gcnt, N, E, nb);
    k_fill<<<(E + TB - 1) / TB, TB>>>(ei, E, curoff, col, is64);

    // L1 fused: agg5 + GEMM(5->64) + relu, prescaled -> h1 (fp16)
    k_l1<<<(N * 8 + TB - 1) / TB, TB>>>(xs, rowptr, col, dinv, W1, b1, h1, N);

    // L2: fp16 agg -> bufB (fp32); mma GEMM(64->128)+b2+relu -> bufA (fp32)
    k_agg64h<false><<<(N + 7) / 8, TB>>>((const __half2*)h1, rowptr, col, dinv,
                                         nullptr, nullptr, is64, bufB,
                                         nullptr, nullptr, N);
    int gtc = (N + 127) / 128;
    k_gemm_mma<64, 128, true, false, false><<<gtc, 256, SM2>>>(bufB, W2, b2, nullptr, bufA, N);

    // L3: mma GEMM(128->64) *dinv -> h3 (fp16); agg + b3 + relu + pool
    k_gemm_mma<128, 64, false, true, true><<<gtc, 256, SM3>>>(bufA, W3, nullptr, dinv, h3, N);
    k_agg64h<true><<<(N + 7) / 8, TB>>>((const __half2*)h3, rowptr, col, dinv, b3,
                                        batch, is64, nullptr, pool, gcnt, N);

    k_final<<<1, NGRAPH>>>(pool, gcnt, Wfc, bfc, out);
}

// round 13
// speedup vs baseline: 1.2189x; 1.1130x over previous
#include <cuda_runtime.h>
#include <cuda_bf16.h>
#include <cuda_fp16.h>
#include <math.h>
#include <stdint.h>

// ---------------- static scratch (no allocations allowed) ----------------
#define MAXN 100000
#define MAXE 1600000
#define NGRAPH 256

__device__ __half g_h1[(size_t)MAXN * 64];    // layer1 out (gather array)
__device__ __half g_t2[(size_t)MAXN * 64];    // agg2 out (GEMM2 input)
__device__ __half g_h2[(size_t)MAXN * 128];   // GEMM2 out (GEMM3 input)
__device__ __half g_h3[(size_t)MAXN * 64];    // GEMM3 out (gather array)
__device__ float  g_xs[(size_t)MAXN * 5];
__device__ int    g_cnt[MAXN];                // zero-init; re-zeroed in k_fill
__device__ int    g_rowptr[MAXN + 1];
__device__ int    g_curoff[MAXN];
__device__ float  g_dinv[MAXN];
__device__ int    g_col[MAXE];
__device__ int    g_bsums[128];
__device__ float  g_pool[NGRAPH * 64];
__device__ float  g_gcnt[NGRAPH];
__device__ int    g_is64[1];

__device__ __forceinline__ int load_idx(const void* p, long long i, int is64) {
    if (is64) return (int)((const long long*)p)[i];
    return ((const int*)p)[i];
}

// split a pair of floats into packed fp16 hi and lo words (lo captures residual)
__device__ __forceinline__ void split2h(float a, float b, uint32_t& hi, uint32_t& lo) {
    __half ah = __float2half_rn(a);
    __half bh = __float2half_rn(b);
    __half al = __float2half_rn(a - __half2float(ah));
    __half bl = __float2half_rn(b - __half2float(bh));
    unsigned short ahu = *(unsigned short*)&ah, bhu = *(unsigned short*)&bh;
    unsigned short alu = *(unsigned short*)&al, blu = *(unsigned short*)&bl;
    hi = ((uint32_t)bhu << 16) | ahu;
    lo = ((uint32_t)blu << 16) | alu;
}

__device__ __forceinline__ void mma16816h(float* d, const uint32_t* a,
                                          uint32_t b0, uint32_t b1) {
    asm volatile(
        "mma.sync.aligned.m16n8k16.row.col.f32.f16.f16.f32 "
        "{%0,%1,%2,%3}, {%4,%5,%6,%7}, {%8,%9}, {%0,%1,%2,%3};"
        : "+f"(d[0]), "+f"(d[1]), "+f"(d[2]), "+f"(d[3])
        : "r"(a[0]), "r"(a[1]), "r"(a[2]), "r"(a[3]), "r"(b0), "r"(b1));
}

// ---------------- degree count (+ per-block dtype detect) ----------------
__global__ void k_count(const void* __restrict__ ei, int E, int* cnt, int* flag) {
    __shared__ int any;
    if (threadIdx.x == 0) any = 0;
    __syncthreads();
    const int* probe = (const int*)ei;
    int loc = 0;
    for (int q = threadIdx.x; q < 512; q += blockDim.x)
        if (probe[2 * q + 1] != 0) loc = 1;
    if (loc) atomicOr(&any, 1);
    __syncthreads();
    int is64 = any ? 0 : 1;
    if (blockIdx.x == 0 && threadIdx.x == 0) flag[0] = is64;   // for later kernels
    int e = blockIdx.x * blockDim.x + threadIdx.x;
    if (e < E) {
        int d = load_idx(ei, (long long)E + e, is64);
        atomicAdd(&cnt[d], 1);
    }
}

__global__ void k_scan1(const int* __restrict__ cnt, int* rowptr, int* bsums, int n) {
    __shared__ int s[1024];
    int i = blockIdx.x * 1024 + threadIdx.x;
    int v = (i < n) ? cnt[i] : 0;
    s[threadIdx.x] = v;
    __syncthreads();
    for (int off = 1; off < 1024; off <<= 1) {
        int t = 0;
        if ((int)threadIdx.x >= off) t = s[threadIdx.x - off];
        __syncthreads();
        s[threadIdx.x] += t;
        __syncthreads();
    }
    if (i < n) rowptr[i] = s[threadIdx.x] - v;
    if (threadIdx.x == 1023) bsums[blockIdx.x] = s[1023];
}

// scan finalize + dinv + x prescale + pool zero (fused); barriers non-divergent.
__global__ void k_scan3(int* rowptr, int* curoff, const int* __restrict__ bsums,
                        const int* __restrict__ cnt, float* dinv,
                        const float* __restrict__ x, float* xs,
                        float* pool, float* gcnt, int n, int E, int nb) {
    __shared__ int pb[128];
    __shared__ int ws[4];
    int t = threadIdx.x;
    int v = 0, orig = 0;
    if (t < 128) {
        v = (t < nb) ? bsums[t] : 0;
        orig = v;
#pragma unroll
        for (int off = 1; off < 32; off <<= 1) {
            int u = __shfl_up_sync(0xffffffffu, v, off);
            if ((t & 31) >= off) v += u;
        }
        if ((t & 31) == 31) ws[t >> 5] = v;
    }
    __syncthreads();
    if (t == 0) { int a = 0; for (int q = 0; q < 4; q++) { int xq = ws[q]; ws[q] = a; a += xq; } }
    __syncthreads();
    if (t < 128) pb[t] = v - orig + ws[t >> 5];
    __syncthreads();

    int i = blockIdx.x * blockDim.x + t;
    if (i < n) {
        int r = rowptr[i] + pb[i >> 10];
        rowptr[i] = r;
        curoff[i] = r;
        float d = rsqrtf((float)cnt[i] + 1.0f);
        dinv[i] = d;
#pragma unroll
        for (int k = 0; k < 5; k++) xs[(size_t)i * 5 + k] = d * x[(size_t)i * 5 + k];
    }
    if (i < NGRAPH * 64) pool[i] = 0.f;
    if (i < NGRAPH) gcnt[i] = 0.f;
    if (i == 0) rowptr[n] = E;
}

// CSR fill; also re-zeroes cnt (its last consumer was scan3) for the next call.
__global__ void k_fill(const void* __restrict__ ei, int E, int n,
                       int* curoff, int* col, int* cnt, const int* flag) {
    int is64 = flag[0];
    int e = blockIdx.x * blockDim.x + threadIdx.x;
    if (e < n) cnt[e] = 0;
    if (e >= E) return;
    int s = load_idx(ei, e, is64);
    int d = load_idx(ei, (long long)E + e, is64);
    int p = atomicAdd(&curoff[d], 1);
    col[p] = s;
}

// ---------------- fused layer1: agg(xs) + GEMM(5->64) + relu -> fp16 --------
__global__ void k_l1(const float* __restrict__ xs,
                     const int* __restrict__ rowptr, const int* __restrict__ col,
                     const float* __restrict__ dinv,
                     const float* __restrict__ W1, const float* __restrict__ b1,
                     __half* __restrict__ out, int n) {
    __shared__ float Ws[5 * 64];
    __shared__ float bs[64];
    int t = threadIdx.x;
    for (int i = t; i < 5 * 64; i += 256) Ws[i] = W1[i];
    if (t < 64) bs[t] = b1[t];
    __syncthreads();

    int gt = blockIdx.x * 256 + t;
    int node = gt >> 3;
    int f = gt & 7;
    bool live = (node < n);
    int nodec = live ? node : (n - 1);

    int beg = rowptr[nodec], end = rowptr[nodec + 1];
    bool valid = (f < 5);
    float acc = 0.f;
    int e = beg;
    for (; e + 3 < end; e += 4) {
        int s0 = col[e], s1 = col[e + 1], s2 = col[e + 2], s3 = col[e + 3];
        float v0 = 0.f, v1 = 0.f, v2 = 0.f, v3 = 0.f;
        if (valid) {
            v0 = __ldg(&xs[(size_t)s0 * 5 + f]);
            v1 = __ldg(&xs[(size_t)s1 * 5 + f]);
            v2 = __ldg(&xs[(size_t)s2 * 5 + f]);
            v3 = __ldg(&xs[(size_t)s3 * 5 + f]);
        }
        acc += (v0 + v1) + (v2 + v3);
    }
    for (; e < end; e++) {
        int s = col[e];
        if (valid) acc += __ldg(&xs[(size_t)s * 5 + f]);
    }
    float ds = dinv[nodec];
    if (valid) acc = ds * (acc + xs[(size_t)nodec * 5 + f]);

    float v[5];
#pragma unroll
    for (int k = 0; k < 5; k++) v[k] = __shfl_sync(0xffffffffu, acc, k, 8);

    int cb = f * 8;
    float o[8];
#pragma unroll
    for (int j = 0; j < 8; j++) {
        float a = bs[cb + j];
#pragma unroll
        for (int k = 0; k < 5; k++) a += v[k] * Ws[k * 64 + cb + j];
        o[j] = fmaxf(a, 0.f) * ds;
    }
    if (live) {
        __half2 q0 = __float22half2_rn(make_float2(o[0], o[1]));
        __half2 q1 = __float22half2_rn(make_float2(o[2], o[3]));
        __half2 q2 = __float22half2_rn(make_float2(o[4], o[5]));
        __half2 q3 = __float22half2_rn(make_float2(o[6], o[7]));
        uint4 u;
        u.x = *(uint32_t*)&q0; u.y = *(uint32_t*)&q1;
        u.z = *(uint32_t*)&q2; u.w = *(uint32_t*)&q3;
        *reinterpret_cast<uint4*>(&out[(size_t)node * 64 + cb]) = u;
    }
}

// ---------------- agg width 64 on fp16: warp/node, half2 loads, 4x unroll ----
// POOL=false: write fp16 (for GEMM2 input). POOL=true: bias+relu+mean-pool.
template <bool POOL>
__global__ void k_agg64h(const __half2* __restrict__ h,
                         const int* __restrict__ rowptr, const int* __restrict__ col,
                         const float* __restrict__ dinv,
                         const float* __restrict__ bias,
                         const void* __restrict__ batch, const int* flag,
                         __half2* __restrict__ out, float* pool, float* gcnt, int n) {
    int node = blockIdx.x * 8 + (threadIdx.x >> 5);
    int lane = threadIdx.x & 31;
    if (node >= n) return;
    int beg = rowptr[node], end = rowptr[node + 1];
    float a0 = 0.f, a1 = 0.f;
    int e = beg;
    for (; e + 3 < end; e += 4) {
        int s0 = col[e], s1 = col[e + 1], s2 = col[e + 2], s3 = col[e + 3];
        float2 f0 = __half22float2(__ldg(&h[(size_t)s0 * 32 + lane]));
        float2 f1 = __half22float2(__ldg(&h[(size_t)s1 * 32 + lane]));
        float2 f2 = __half22float2(__ldg(&h[(size_t)s2 * 32 + lane]));
        float2 f3 = __half22float2(__ldg(&h[(size_t)s3 * 32 + lane]));
        a0 += (f0.x + f1.x) + (f2.x + f3.x);
        a1 += (f0.y + f1.y) + (f2.y + f3.y);
    }
    for (; e < end; e++) {
        int s = col[e];
        float2 f = __half22float2(__ldg(&h[(size_t)s * 32 + lane]));
        a0 += f.x;
        a1 += f.y;
    }
    float2 self = __half22float2(h[(size_t)node * 32 + lane]);
    float ds = dinv[node];
    a0 = ds * (a0 + self.x);
    a1 = ds * (a1 + self.y);
    if (POOL) {
        a0 = fmaxf(a0 + __ldg(&bias[2 * lane]), 0.f);
        a1 = fmaxf(a1 + __ldg(&bias[2 * lane + 1]), 0.f);
        int g = load_idx(batch, node, flag[0]);
        atomicAdd(&pool[g * 64 + 2 * lane], a0);
        atomicAdd(&pool[g * 64 + 2 * lane + 1], a1);
        if (lane == 0) atomicAdd(&gcnt[g], 1.0f);
    } else {
        out[(size_t)node * 32 + lane] = __float22half2_rn(make_float2(a0, a1));
    }
}

// ---------------- fp16 mma GEMM: A fp16 (direct), W fp32->fp16 hi/lo (2 terms)
// D[128,NC] = A[128,K] @ W[K,NC]; fp32 accum. 8 warps, warp = 16 rows x NC.
template <int K, int NC, bool RELU, bool SCALE>
__launch_bounds__(256)
__global__ void k_gemm_f16(const __half* __restrict__ A, const float* __restrict__ W,
                           const float* __restrict__ bias, const float* __restrict__ dinv,
                           __half* __restrict__ out, int n) {
    constexpr int P = K + 8;
    extern __shared__ char sm[];
    uint16_t* As = (uint16_t*)sm;              // [128][P]
    uint16_t* Bh = As + 128 * P;               // [NC][P]
    uint16_t* Bl = Bh + NC * P;

    const int tid = threadIdx.x;
    const int nodeBase = blockIdx.x * 128;

    // A: direct fp16 copy (vectorized, 8 halves per thread-iteration)
    for (int q = tid; q < 128 * (K / 8); q += 256) {
        int r = q / (K / 8);
        int c8 = (q % (K / 8)) * 8;
        int gn = nodeBase + r;
        uint4 v = make_uint4(0u, 0u, 0u, 0u);
        if (gn < n) v = *reinterpret_cast<const uint4*>(&A[(size_t)gn * K + c8]);
        *reinterpret_cast<uint4*>(&As[r * P + c8]) = v;
    }
    // B: W[K][NC] fp32 -> Bsm[n][k] fp16 hi/lo
    for (int q = tid; q < NC * (K / 2); q += 256) {
        int nrow = q % NC;
        int k2 = (q / NC) * 2;
        float a = __ldg(&W[(size_t)k2 * NC + nrow]);
        float b = __ldg(&W[(size_t)(k2 + 1) * NC + nrow]);
        uint32_t h, l;
        split2h(a, b, h, l);
        *(uint32_t*)&Bh[nrow * P + k2] = h;
        *(uint32_t*)&Bl[nrow * P + k2] = l;
    }
    __syncthreads();

    const int wid = tid >> 5;
    const int lane = tid & 31;
    const int g = lane >> 2;
    const int t4 = lane & 3;
    const int warpRow = wid * 16;

    float acc[NC / 8][4];
#pragma unroll
    for (int nt = 0; nt < NC / 8; nt++)
#pragma unroll
        for (int j = 0; j < 4; j++) acc[nt][j] = 0.f;

#pragma unroll
    for (int ks = 0; ks < K / 16; ks++) {
        int k0 = ks * 16;
        int r0 = warpRow + g;
        uint32_t af[4];
        af[0] = *(uint32_t*)&As[r0 * P + k0 + 2 * t4];
        af[1] = *(uint32_t*)&As[(r0 + 8) * P + k0 + 2 * t4];
        af[2] = *(uint32_t*)&As[r0 * P + k0 + 2 * t4 + 8];
        af[3] = *(uint32_t*)&As[(r0 + 8) * P + k0 + 2 * t4 + 8];
#pragma unroll
        for (int nt = 0; nt < NC / 8; nt++) {
            int nr = nt * 8 + g;
            uint32_t bh0 = *(uint32_t*)&Bh[nr * P + k0 + 2 * t4];
            uint32_t bh1 = *(uint32_t*)&Bh[nr * P + k0 + 2 * t4 + 8];
            uint32_t bl0 = *(uint32_t*)&Bl[nr * P + k0 + 2 * t4];
            uint32_t bl1 = *(uint32_t*)&Bl[nr * P + k0 + 2 * t4 + 8];
            mma16816h(acc[nt], af, bh0, bh1);
            mma16816h(acc[nt], af, bl0, bl1);
        }
    }

    int row0 = nodeBase + warpRow + g;
    int row1 = row0 + 8;
    bool l0 = row0 < n, l1 = row1 < n;
    float ds0 = (SCALE && l0) ? dinv[row0] : 1.0f;
    float ds1 = (SCALE && l1) ? dinv[row1] : 1.0f;
#pragma unroll
    for (int nt = 0; nt < NC / 8; nt++) {
        int colc = nt * 8 + 2 * t4;
        float b0 = RELU ? __ldg(&bias[colc]) : 0.f;
        float b1 = RELU ? __ldg(&bias[colc + 1]) : 0.f;
        float v0 = acc[nt][0], v1 = acc[nt][1], v2 = acc[nt][2], v3 = acc[nt][3];
        if (RELU) {
            v0 = fmaxf(v0 + b0, 0.f); v1 = fmaxf(v1 + b1, 0.f);
            v2 = fmaxf(v2 + b0, 0.f); v3 = fmaxf(v3 + b1, 0.f);
        }
        if (SCALE) { v0 *= ds0; v1 *= ds0; v2 *= ds1; v3 *= ds1; }
        if (l0) {
            __half2 hh = __float22half2_rn(make_float2(v0, v1));
            *(uint32_t*)&out[(size_t)row0 * NC + colc] = *(uint32_t*)&hh;
        }
        if (l1) {
            __half2 hh = __float22half2_rn(make_float2(v2, v3));
            *(uint32_t*)&out[(size_t)row1 * NC + colc] = *(uint32_t*)&hh;
        }
    }
}

// ---------------- final FC + sigmoid ----------------
__global__ void k_final(const float* __restrict__ pool, const float* __restrict__ gcnt,
                        const float* __restrict__ Wfc, const float* __restrict__ bfc,
                        float* __restrict__ out) {
    int g = threadIdx.x;
    float c = fmaxf(gcnt[g], 1.0f);
    float acc = 0.f;
#pragma unroll
    for (int k = 0; k < 64; k++) acc += pool[g * 64 + k] * Wfc[k];
    acc = acc / c + bfc[0];
    out[g] = 1.f / (1.f + expf(-acc));
}

// ---------------- launch ----------------
extern "C" void kernel_launch(void* const* d_in, const int* in_sizes, int n_in,
                              void* d_out, int out_size) {
    const float*  x     = (const float*)d_in[0];
    const void*   ei    = d_in[1];
    const void*   batch = d_in[2];
    const float*  W1    = (const float*)d_in[3];
    const float*  b1    = (const float*)d_in[4];
    const float*  W2    = (const float*)d_in[5];
    const float*  b2    = (const float*)d_in[6];
    const float*  W3    = (const float*)d_in[7];
    const float*  b3    = (const float*)d_in[8];
    const float*  Wfc   = (const float*)d_in[9];
    const float*  bfc   = (const float*)d_in[10];
    float*        out   = (float*)d_out;

    const int N = in_sizes[0] / 5;
    const int E = in_sizes[1] / 2;

    float *xs, *dinv, *pool, *gcnt;
    __half *h1, *t2, *h2, *h3;
    int *cnt, *rowptr, *curoff, *col, *bsums, *is64;
    cudaGetSymbolAddress((void**)&h1, g_h1);
    cudaGetSymbolAddress((void**)&t2, g_t2);
    cudaGetSymbolAddress((void**)&h2, g_h2);
    cudaGetSymbolAddress((void**)&h3, g_h3);
    cudaGetSymbolAddress((void**)&xs, g_xs);
    cudaGetSymbolAddress((void**)&dinv, g_dinv);
    cudaGetSymbolAddress((void**)&pool, g_pool);
    cudaGetSymbolAddress((void**)&gcnt, g_gcnt);
    cudaGetSymbolAddress((void**)&cnt, g_cnt);
    cudaGetSymbolAddress((void**)&rowptr, g_rowptr);
    cudaGetSymbolAddress((void**)&curoff, g_curoff);
    cudaGetSymbolAddress((void**)&col, g_col);
    cudaGetSymbolAddress((void**)&bsums, g_bsums);
    cudaGetSymbolAddress((void**)&is64, g_is64);

    // smem: gemm2 (K=64,P=72): (128+2*128)*72*2 = 55296 B
    //       gemm3 (K=128,P=136): (128+2*64)*136*2 = 69632 B
    const int SM2 = (128 + 2 * 128) * (64 + 8) * 2;
    const int SM3 = (128 + 2 * 64) * (128 + 8) * 2;
    static int smem_set = 0;
    if (!smem_set) {
        cudaFuncSetAttribute(k_gemm_f16<64, 128, true, false>,
                             cudaFuncAttributeMaxDynamicSharedMemorySize, SM2);
        cudaFuncSetAttribute(k_gemm_f16<128, 64, false, true>,
                             cudaFuncAttributeMaxDynamicSharedMemorySize, SM3);
        smem_set = 1;
    }

    const int TB = 256;
    k_count<<<(E + TB - 1) / TB, TB>>>(ei, E, cnt, is64);

    int nb = (N + 1023) / 1024;
    k_scan1<<<nb, 1024>>>(cnt, rowptr, bsums, N);
    k_scan3<<<(N + TB - 1) / TB, TB>>>(rowptr, curoff, bsums, cnt, dinv, x, xs,
                                       pool, gcnt, N, E, nb);
    k_fill<<<(E + TB - 1) / TB, TB>>>(ei, E, N, curoff, col, cnt, is64);

    // L1 fused: agg5 + GEMM(5->64) + relu, prescaled -> h1 (fp16)
    k_l1<<<(N * 8 + TB - 1) / TB, TB>>>(xs, rowptr, col, dinv, W1, b1, h1, N);

    // L2: fp16 agg -> t2 (fp16); fp16 mma GEMM(64->128)+b2+relu -> h2 (fp16)
    k_agg64h<false><<<(N + 7) / 8, TB>>>((const __half2*)h1, rowptr, col, dinv,
                                         nullptr, nullptr, is64, (__half2*)t2,
                                         nullptr, nullptr, N);
    int gtc = (N + 127) / 128;
    k_gemm_f16<64, 128, true, false><<<gtc, 256, SM2>>>(t2, W2, b2, nullptr, h2, N);

    // L3: fp16 mma GEMM(128->64) *dinv -> h3 (fp16); agg + b3 + relu + pool
    k_gemm_f16<128, 64, false, true><<<gtc, 256, SM3>>>(h2, W3, nullptr, dinv, h3, N);
    k_agg64h<true><<<(N + 7) / 8, TB>>>((const __half2*)h3, rowptr, col, dinv, b3,
                                        batch, is64, nullptr, pool, gcnt, N);

    k_final<<<1, NGRAPH>>>(pool, gcnt, Wfc, bfc, out);
}

// round 14
// speedup vs baseline: 1.5653x; 1.2842x over previous
#include <cuda_runtime.h>
#include <cuda_bf16.h>
#include <cuda_fp16.h>
#include <math.h>
#include <stdint.h>

// ---------------- static scratch (no allocations allowed) ----------------
#define MAXN 100000
#define MAXE 1600000
#define NGRAPH 256

__device__ __half g_h1[(size_t)MAXN * 64];    // layer1 out (gather array)
__device__ __half g_t2[(size_t)MAXN * 64];    // agg2 out (GEMM2 input)
__device__ __half g_h2[(size_t)MAXN * 128];   // GEMM2 out (GEMM3 input)
__device__ __half g_h3[(size_t)MAXN * 64];    // GEMM3 out (gather array)
__device__ __half g_w2h[128 * 64];            // W2 as [n][k] fp16 hi
__device__ __half g_w2l[128 * 64];            // W2 lo
__device__ __half g_w3h[64 * 128];            // W3 as [n][k] fp16 hi
__device__ __half g_w3l[64 * 128];            // W3 lo
__device__ float  g_xs[(size_t)MAXN * 5];
__device__ int    g_cnt[MAXN];                // zero-init; re-zeroed in scan3
__device__ int    g_rowptr[MAXN + 1];
__device__ int    g_curoff[MAXN];
__device__ float  g_dinv[MAXN];
__device__ int    g_col[MAXE];
__device__ int    g_bsums[128];
__device__ float  g_pool[NGRAPH * 64];
__device__ float  g_gcnt[NGRAPH];
__device__ int    g_is64[1];

__device__ __forceinline__ int load_idx(const void* p, long long i, int is64) {
    if (is64) return (int)((const long long*)p)[i];
    return ((const int*)p)[i];
}

__device__ __forceinline__ void split2h(float a, float b, uint32_t& hi, uint32_t& lo) {
    __half ah = __float2half_rn(a);
    __half bh = __float2half_rn(b);
    __half al = __float2half_rn(a - __half2float(ah));
    __half bl = __float2half_rn(b - __half2float(bh));
    unsigned short ahu = *(unsigned short*)&ah, bhu = *(unsigned short*)&bh;
    unsigned short alu = *(unsigned short*)&al, blu = *(unsigned short*)&bl;
    hi = ((uint32_t)bhu << 16) | ahu;
    lo = ((uint32_t)blu << 16) | alu;
}

__device__ __forceinline__ void mma16816h(float* d, const uint32_t* a,
                                          uint32_t b0, uint32_t b1) {
    asm volatile(
        "mma.sync.aligned.m16n8k16.row.col.f32.f16.f16.f32 "
        "{%0,%1,%2,%3}, {%4,%5,%6,%7}, {%8,%9}, {%0,%1,%2,%3};"
        : "+f"(d[0]), "+f"(d[1]), "+f"(d[2]), "+f"(d[3])
        : "r"(a[0]), "r"(a[1]), "r"(a[2]), "r"(a[3]), "r"(b0), "r"(b1));
}

// ---------------- degree count (+ per-block dtype detect) ----------------
__global__ void k_count(const void* __restrict__ ei, int E, int* cnt, int* flag) {
    __shared__ int any;
    if (threadIdx.x == 0) any = 0;
    __syncthreads();
    const int* probe = (const int*)ei;
    int loc = 0;
    for (int q = threadIdx.x; q < 512; q += blockDim.x)
        if (probe[2 * q + 1] != 0) loc = 1;
    if (loc) atomicOr(&any, 1);
    __syncthreads();
    int is64 = any ? 0 : 1;
    if (blockIdx.x == 0 && threadIdx.x == 0) flag[0] = is64;
    int e = blockIdx.x * blockDim.x + threadIdx.x;
    if (e < E) {
        int d = load_idx(ei, (long long)E + e, is64);
        atomicAdd(&cnt[d], 1);
    }
}

__global__ void k_scan1(const int* __restrict__ cnt, int* rowptr, int* bsums, int n) {
    __shared__ int s[1024];
    int i = blockIdx.x * 1024 + threadIdx.x;
    int v = (i < n) ? cnt[i] : 0;
    s[threadIdx.x] = v;
    __syncthreads();
    for (int off = 1; off < 1024; off <<= 1) {
        int t = 0;
        if ((int)threadIdx.x >= off) t = s[threadIdx.x - off];
        __syncthreads();
        s[threadIdx.x] += t;
        __syncthreads();
    }
    if (i < n) rowptr[i] = s[threadIdx.x] - v;
    if (threadIdx.x == 1023) bsums[blockIdx.x] = s[1023];
}

// scan finalize + dinv + x prescale + pool zero + cnt re-zero (fused)
__global__ void k_scan3(int* rowptr, int* curoff, const int* __restrict__ bsums,
                        int* cnt, float* dinv,
                        const float* __restrict__ x, float* xs,
                        float* pool, float* gcnt, int n, int E, int nb) {
    __shared__ int pb[128];
    __shared__ int ws[4];
    int t = threadIdx.x;
    int v = 0, orig = 0;
    if (t < 128) {
        v = (t < nb) ? bsums[t] : 0;
        orig = v;
#pragma unroll
        for (int off = 1; off < 32; off <<= 1) {
            int u = __shfl_up_sync(0xffffffffu, v, off);
            if ((t & 31) >= off) v += u;
        }
        if ((t & 31) == 31) ws[t >> 5] = v;
    }
    __syncthreads();
    if (t == 0) { int a = 0; for (int q = 0; q < 4; q++) { int xq = ws[q]; ws[q] = a; a += xq; } }
    __syncthreads();
    if (t < 128) pb[t] = v - orig + ws[t >> 5];
    __syncthreads();

    int i = blockIdx.x * blockDim.x + t;
    if (i < n) {
        int r = rowptr[i] + pb[i >> 10];
        rowptr[i] = r;
        curoff[i] = r;
        float d = rsqrtf((float)cnt[i] + 1.0f);
        cnt[i] = 0;                                 // re-zero for next call
        dinv[i] = d;
#pragma unroll
        for (int k = 0; k < 5; k++) xs[(size_t)i * 5 + k] = d * x[(size_t)i * 5 + k];
    }
    if (i < NGRAPH * 64) pool[i] = 0.f;
    if (i < NGRAPH) gcnt[i] = 0.f;
    if (i == 0) rowptr[n] = E;
}

// CSR fill; extra blocks (>= eb) pre-convert W2/W3 to fp16 hi/lo [n][k].
__global__ void k_fill(const void* __restrict__ ei, int E, int eb,
                       int* curoff, int* col, const int* flag,
                       const float* __restrict__ W2, const float* __restrict__ W3,
                       __half* w2h, __half* w2l, __half* w3h, __half* w3l) {
    if ((int)blockIdx.x >= eb) {
        int idx = (blockIdx.x - eb) * 256 + threadIdx.x;   // 0..16383
        if (idx < 8192) {                                   // W2: [64][128] -> [n=128][k=64]
            int nrow = idx % 128;
            int k = idx / 128;
            float w = __ldg(&W2[(size_t)k * 128 + nrow]);
            __half h = __float2half_rn(w);
            __half l = __float2half_rn(w - __half2float(h));
            w2h[nrow * 64 + k] = h;
            w2l[nrow * 64 + k] = l;
        } else {                                            // W3: [128][64] -> [n=64][k=128]
            int j = idx - 8192;
            int nrow = j % 64;
            int k = j / 64;
            float w = __ldg(&W3[(size_t)k * 64 + nrow]);
            __half h = __float2half_rn(w);
            __half l = __float2half_rn(w - __half2float(h));
            w3h[nrow * 128 + k] = h;
            w3l[nrow * 128 + k] = l;
        }
        return;
    }
    int is64 = flag[0];
    int e = blockIdx.x * blockDim.x + threadIdx.x;
    if (e >= E) return;
    int s = load_idx(ei, e, is64);
    int d = load_idx(ei, (long long)E + e, is64);
    int p = atomicAdd(&curoff[d], 1);
    col[p] = s;
}

// ---------------- fused layer1: agg(xs) + GEMM(5->64) + relu -> fp16 --------
__global__ void k_l1(const float* __restrict__ xs,
                     const int* __restrict__ rowptr, const int* __restrict__ col,
                     const float* __restrict__ dinv,
                     const float* __restrict__ W1, const float* __restrict__ b1,
                     __half* __restrict__ out, int n) {
    __shared__ float Ws[5 * 64];
    __shared__ float bs[64];
    int t = threadIdx.x;
    for (int i = t; i < 5 * 64; i += 256) Ws[i] = W1[i];
    if (t < 64) bs[t] = b1[t];
    __syncthreads();

    int gt = blockIdx.x * 256 + t;
    int node = gt >> 3;
    int f = gt & 7;
    bool live = (node < n);
    int nodec = live ? node : (n - 1);

    int beg = rowptr[nodec], end = rowptr[nodec + 1];
    bool valid = (f < 5);
    float acc = 0.f;
    int e = beg;
    for (; e + 3 < end; e += 4) {
        int s0 = col[e], s1 = col[e + 1], s2 = col[e + 2], s3 = col[e + 3];
        float v0 = 0.f, v1 = 0.f, v2 = 0.f, v3 = 0.f;
        if (valid) {
            v0 = __ldg(&xs[(size_t)s0 * 5 + f]);
            v1 = __ldg(&xs[(size_t)s1 * 5 + f]);
            v2 = __ldg(&xs[(size_t)s2 * 5 + f]);
            v3 = __ldg(&xs[(size_t)s3 * 5 + f]);
        }
        acc += (v0 + v1) + (v2 + v3);
    }
    for (; e < end; e++) {
        int s = col[e];
        if (valid) acc += __ldg(&xs[(size_t)s * 5 + f]);
    }
    float ds = dinv[nodec];
    if (valid) acc = ds * (acc + xs[(size_t)nodec * 5 + f]);

    float v[5];
#pragma unroll
    for (int k = 0; k < 5; k++) v[k] = __shfl_sync(0xffffffffu, acc, k, 8);

    int cb = f * 8;
    float o[8];
#pragma unroll
    for (int j = 0; j < 8; j++) {
        float a = bs[cb + j];
#pragma unroll
        for (int k = 0; k < 5; k++) a += v[k] * Ws[k * 64 + cb + j];
        o[j] = fmaxf(a, 0.f) * ds;
    }
    if (live) {
        __half2 q0 = __float22half2_rn(make_float2(o[0], o[1]));
        __half2 q1 = __float22half2_rn(make_float2(o[2], o[3]));
        __half2 q2 = __float22half2_rn(make_float2(o[4], o[5]));
        __half2 q3 = __float22half2_rn(make_float2(o[6], o[7]));
        uint4 u;
        u.x = *(uint32_t*)&q0; u.y = *(uint32_t*)&q1;
        u.z = *(uint32_t*)&q2; u.w = *(uint32_t*)&q3;
        *reinterpret_cast<uint4*>(&out[(size_t)node * 64 + cb]) = u;
    }
}

// ---------------- agg width 64 on fp16 (no pool): warp/node ----------------
__global__ void k_agg64h(const __half2* __restrict__ h,
                         const int* __restrict__ rowptr, const int* __restrict__ col,
                         const float* __restrict__ dinv,
                         __half2* __restrict__ out, int n) {
    int node = blockIdx.x * 8 + (threadIdx.x >> 5);
    int lane = threadIdx.x & 31;
    if (node >= n) return;
    int beg = rowptr[node], end = rowptr[node + 1];
    float a0 = 0.f, a1 = 0.f;
    int e = beg;
    for (; e + 3 < end; e += 4) {
        int s0 = col[e], s1 = col[e + 1], s2 = col[e + 2], s3 = col[e + 3];
        float2 f0 = __half22float2(__ldg(&h[(size_t)s0 * 32 + lane]));
        float2 f1 = __half22float2(__ldg(&h[(size_t)s1 * 32 + lane]));
        float2 f2 = __half22float2(__ldg(&h[(size_t)s2 * 32 + lane]));
        float2 f3 = __half22float2(__ldg(&h[(size_t)s3 * 32 + lane]));
        a0 += (f0.x + f1.x) + (f2.x + f3.x);
        a1 += (f0.y + f1.y) + (f2.y + f3.y);
    }
    for (; e < end; e++) {
        int s = col[e];
        float2 f = __half22float2(__ldg(&h[(size_t)s * 32 + lane]));
        a0 += f.x;
        a1 += f.y;
    }
    float2 self = __half22float2(h[(size_t)node * 32 + lane]);
    float ds = dinv[node];
    a0 = ds * (a0 + self.x);
    a1 = ds * (a1 + self.y);
    out[(size_t)node * 32 + lane] = __float22half2_rn(make_float2(a0, a1));
}

// ---------------- agg + bias + relu + mean-pool, smem-reduced atomics -------
__global__ void k_aggpool(const __half2* __restrict__ h,
                          const int* __restrict__ rowptr, const int* __restrict__ col,
                          const float* __restrict__ dinv,
                          const float* __restrict__ bias,
                          const void* __restrict__ batch, const int* flag,
                          float* pool, float* gcnt, int n) {
    __shared__ float acc[2][64];
    __shared__ int sg[8];
    int wid = threadIdx.x >> 5;
    int lane = threadIdx.x & 31;
    int node = blockIdx.x * 8 + wid;
    bool live = node < n;

    float a0 = 0.f, a1 = 0.f;
    int g = -1;
    if (live) {
        int beg = rowptr[node], end = rowptr[node + 1];
        int e = beg;
        for (; e + 3 < end; e += 4) {
            int s0 = col[e], s1 = col[e + 1], s2 = col[e + 2], s3 = col[e + 3];
            float2 f0 = __half22float2(__ldg(&h[(size_t)s0 * 32 + lane]));
            float2 f1 = __half22float2(__ldg(&h[(size_t)s1 * 32 + lane]));
            float2 f2 = __half22float2(__ldg(&h[(size_t)s2 * 32 + lane]));
            float2 f3 = __half22float2(__ldg(&h[(size_t)s3 * 32 + lane]));
            a0 += (f0.x + f1.x) + (f2.x + f3.x);
            a1 += (f0.y + f1.y) + (f2.y + f3.y);
        }
        for (; e < end; e++) {
            int s = col[e];
            float2 f = __half22float2(__ldg(&h[(size_t)s * 32 + lane]));
            a0 += f.x;
            a1 += f.y;
        }
        float2 self = __half22float2(h[(size_t)node * 32 + lane]);
        float ds = dinv[node];
        a0 = fmaxf(ds * (a0 + self.x) + __ldg(&bias[2 * lane]), 0.f);
        a1 = fmaxf(ds * (a1 + self.y) + __ldg(&bias[2 * lane + 1]), 0.f);
        g = load_idx(batch, node, flag[0]);
    }
    if (lane == 0) sg[wid] = live ? g : -1;
    for (int i = threadIdx.x; i < 128; i += 256) acc[i >> 6][i & 63] = 0.f;
    __syncthreads();

    int gmin = 0x7fffffff, gmax = -1;
#pragma unroll
    for (int w = 0; w < 8; w++) {
        int gg = sg[w];
        if (gg >= 0) { gmin = min(gmin, gg); gmax = max(gmax, gg); }
    }
    bool fast = (gmax >= 0) && (gmax - gmin <= 1);

    if (live) {
        if (fast) {
            atomicAdd(&acc[g - gmin][2 * lane], a0);
            atomicAdd(&acc[g - gmin][2 * lane + 1], a1);
        } else {
            atomicAdd(&pool[g * 64 + 2 * lane], a0);
            atomicAdd(&pool[g * 64 + 2 * lane + 1], a1);
            if (lane == 0) atomicAdd(&gcnt[g], 1.0f);
        }
    }
    __syncthreads();
    if (fast) {
        int t = threadIdx.x;
        if (t < 128) {
            int r = t >> 6, f = t & 63;
            if (gmin + r <= gmax) {
                float v = acc[r][f];
                atomicAdd(&pool[(gmin + r) * 64 + f], v);
            }
        }
        if (t < 2 && gmin + t <= gmax) {
            int c = 0;
#pragma unroll
            for (int w = 0; w < 8; w++) if (sg[w] == gmin + (int)t) c++;
            if (c > 0) atomicAdd(&gcnt[gmin + t], (float)c);
        }
    }
}

// ---------------- fp16 mma GEMM: A fp16 direct, W pre-converted hi/lo -------
template <int K, int NC, bool RELU, bool SCALE>
__launch_bounds__(256)
__global__ void k_gemm_f16(const __half* __restrict__ A,
                           const __half* __restrict__ wh, const __half* __restrict__ wl,
                           const float* __restrict__ bias, const float* __restrict__ dinv,
                           __half* __restrict__ out, int n) {
    constexpr int P = K + 8;
    extern __shared__ char sm[];
    uint16_t* As = (uint16_t*)sm;              // [128][P]
    uint16_t* Bh = As + 128 * P;               // [NC][P]
    uint16_t* Bl = Bh + NC * P;

    const int tid = threadIdx.x;
    const int nodeBase = blockIdx.x * 128;

    for (int q = tid; q < 128 * (K / 8); q += 256) {
        int r = q / (K / 8);
        int c8 = (q % (K / 8)) * 8;
        int gn = nodeBase + r;
        uint4 v = make_uint4(0u, 0u, 0u, 0u);
        if (gn < n) v = *reinterpret_cast<const uint4*>(&A[(size_t)gn * K + c8]);
        *reinterpret_cast<uint4*>(&As[r * P + c8]) = v;
    }
    for (int q = tid; q < NC * (K / 8); q += 256) {
        int nrow = q / (K / 8);
        int c8 = (q % (K / 8)) * 8;
        *reinterpret_cast<uint4*>(&Bh[nrow * P + c8]) =
            *reinterpret_cast<const uint4*>(&wh[(size_t)nrow * K + c8]);
        *reinterpret_cast<uint4*>(&Bl[nrow * P + c8]) =
            *reinterpret_cast<const uint4*>(&wl[(size_t)nrow * K + c8]);
    }
    __syncthreads();

    const int wid = tid >> 5;
    const int lane = tid & 31;
    const int g = lane >> 2;
    const int t4 = lane & 3;
    const int warpRow = wid * 16;

    float acc[NC / 8][4];
#pragma unroll
    for (int nt = 0; nt < NC / 8; nt++)
#pragma unroll
        for (int j = 0; j < 4; j++) acc[nt][j] = 0.f;

#pragma unroll
    for (int ks = 0; ks < K / 16; ks++) {
        int k0 = ks * 16;
        int r0 = warpRow + g;
        uint32_t af[4];
        af[0] = *(uint32_t*)&As[r0 * P + k0 + 2 * t4];
        af[1] = *(uint32_t*)&As[(r0 + 8) * P + k0 + 2 * t4];
        af[2] = *(uint32_t*)&As[r0 * P + k0 + 2 * t4 + 8];
        af[3] = *(uint32_t*)&As[(r0 + 8) * P + k0 + 2 * t4 + 8];
#pragma unroll
        for (int nt = 0; nt < NC / 8; nt++) {
            int nr = nt * 8 + g;
            uint32_t bh0 = *(uint32_t*)&Bh[nr * P + k0 + 2 * t4];
            uint32_t bh1 = *(uint32_t*)&Bh[nr * P + k0 + 2 * t4 + 8];
            uint32_t bl0 = *(uint32_t*)&Bl[nr * P + k0 + 2 * t4];
            uint32_t bl1 = *(uint32_t*)&Bl[nr * P + k0 + 2 * t4 + 8];
            mma16816h(acc[nt], af, bh0, bh1);
            mma16816h(acc[nt], af, bl0, bl1);
        }
    }

    int row0 = nodeBase + warpRow + g;
    int row1 = row0 + 8;
    bool l0 = row0 < n, l1 = row1 < n;
    float ds0 = (SCALE && l0) ? dinv[row0] : 1.0f;
    float ds1 = (SCALE && l1) ? dinv[row1] : 1.0f;
#pragma unroll
    for (int nt = 0; nt < NC / 8; nt++) {
        int colc = nt * 8 + 2 * t4;
        float b0 = RELU ? __ldg(&bias[colc]) : 0.f;
        float b1 = RELU ? __ldg(&bias[colc + 1]) : 0.f;
        float v0 = acc[nt][0], v1 = acc[nt][1], v2 = acc[nt][2], v3 = acc[nt][3];
        if (RELU) {
            v0 = fmaxf(v0 + b0, 0.f); v1 = fmaxf(v1 + b1, 0.f);
            v2 = fmaxf(v2 + b0, 0.f); v3 = fmaxf(v3 + b1, 0.f);
        }
        if (SCALE) { v0 *= ds0; v1 *= ds0; v2 *= ds1; v3 *= ds1; }
        if (l0) {
            __half2 hh = __float22half2_rn(make_float2(v0, v1));
            *(uint32_t*)&out[(size_t)row0 * NC + colc] = *(uint32_t*)&hh;
        }
        if (l1) {
            __half2 hh = __float22half2_rn(make_float2(v2, v3));
            *(uint32_t*)&out[(size_t)row1 * NC + colc] = *(uint32_t*)&hh;
        }
    }
}

// ---------------- final FC + sigmoid ----------------
__global__ void k_final(const float* __restrict__ pool, const float* __restrict__ gcnt,
                        const float* __restrict__ Wfc, const float* __restrict__ bfc,
                        float* __restrict__ out) {
    int g = threadIdx.x;
    float c = fmaxf(gcnt[g], 1.0f);
    float acc = 0.f;
#pragma unroll
    for (int k = 0; k < 64; k++) acc += pool[g * 64 + k] * Wfc[k];
    acc = acc / c + bfc[0];
    out[g] = 1.f / (1.f + expf(-acc));
}

// ---------------- launch ----------------
extern "C" void kernel_launch(void* const* d_in, const int* in_sizes, int n_in,
                              void* d_out, int out_size) {
    const float*  x     = (const float*)d_in[0];
    const void*   ei    = d_in[1];
    const void*   batch = d_in[2];
    const float*  W1    = (const float*)d_in[3];
    const float*  b1    = (const float*)d_in[4];
    const float*  W2    = (const float*)d_in[5];
    const float*  b2    = (const float*)d_in[6];
    const float*  W3    = (const float*)d_in[7];
    const float*  b3    = (const float*)d_in[8];
    const float*  Wfc   = (const float*)d_in[9];
    const float*  bfc   = (const float*)d_in[10];
    float*        out   = (float*)d_out;

    const int N = in_sizes[0] / 5;
    const int E = in_sizes[1] / 2;

    float *xs, *dinv, *pool, *gcnt;
    __half *h1, *t2, *h2, *h3, *w2h, *w2l, *w3h, *w3l;
    int *cnt, *rowptr, *curoff, *col, *bsums, *is64;
    cudaGetSymbolAddress((void**)&h1, g_h1);
    cudaGetSymbolAddress((void**)&t2, g_t2);
    cudaGetSymbolAddress((void**)&h2, g_h2);
    cudaGetSymbolAddress((void**)&h3, g_h3);
    cudaGetSymbolAddress((void**)&w2h, g_w2h);
    cudaGetSymbolAddress((void**)&w2l, g_w2l);
    cudaGetSymbolAddress((void**)&w3h, g_w3h);
    cudaGetSymbolAddress((void**)&w3l, g_w3l);
    cudaGetSymbolAddress((void**)&xs, g_xs);
    cudaGetSymbolAddress((void**)&dinv, g_dinv);
    cudaGetSymbolAddress((void**)&pool, g_pool);
    cudaGetSymbolAddress((void**)&gcnt, g_gcnt);
    cudaGetSymbolAddress((void**)&cnt, g_cnt);
    cudaGetSymbolAddress((void**)&rowptr, g_rowptr);
    cudaGetSymbolAddress((void**)&curoff, g_curoff);
    cudaGetSymbolAddress((void**)&col, g_col);
    cudaGetSymbolAddress((void**)&bsums, g_bsums);
    cudaGetSymbolAddress((void**)&is64, g_is64);

    const int SM2 = (128 + 2 * 128) * (64 + 8) * 2;
    const int SM3 = (128 + 2 * 64) * (128 + 8) * 2;
    static int smem_set = 0;
    if (!smem_set) {
        cudaFuncSetAttribute(k_gemm_f16<64, 128, true, false>,
                             cudaFuncAttributeMaxDynamicSharedMemorySize, SM2);
        cudaFuncSetAttribute(k_gemm_f16<128, 64, false, true>,
                             cudaFuncAttributeMaxDynamicSharedMemorySize, SM3);
        smem_set = 1;
    }

    const int TB = 256;
    k_count<<<(E + TB - 1) / TB, TB>>>(ei, E, cnt, is64);

    int nb = (N + 1023) / 1024;
    k_scan1<<<nb, 1024>>>(cnt, rowptr, bsums, N);
    k_scan3<<<(N + TB - 1) / TB, TB>>>(rowptr, curoff, bsums, cnt, dinv, x, xs,
                                       pool, gcnt, N, E, nb);
    int eb = (E + TB - 1) / TB;
    k_fill<<<eb + 64, TB>>>(ei, E, eb, curoff, col, is64, W2, W3, w2h, w2l, w3h, w3l);

    // L1 fused: agg5 + GEMM(5->64) + relu, prescaled -> h1 (fp16)
    k_l1<<<(N * 8 + TB - 1) / TB, TB>>>(xs, rowptr, col, dinv, W1, b1, h1, N);

    // L2: fp16 agg -> t2; fp16 mma GEMM(64->128)+b2+relu -> h2
    k_agg64h<<<(N + 7) / 8, TB>>>((const __half2*)h1, rowptr, col, dinv,
                                  (__half2*)t2, N);
    int gtc = (N + 127) / 128;
    k_gemm_f16<64, 128, true, false><<<gtc, 256, SM2>>>(t2, w2h, w2l, b2, nullptr, h2, N);

    // L3: fp16 mma GEMM(128->64) *dinv -> h3; agg + b3 + relu + pool (reduced atomics)
    k_gemm_f16<128, 64, false, true><<<gtc, 256, SM3>>>(h2, w3h, w3l, nullptr, dinv, h3, N);
    k_aggpool<<<(N + 7) / 8, TB>>>((const __half2*)h3, rowptr, col, dinv, b3,
                                   batch, is64, pool, gcnt, N);

    k_final<<<1, NGRAPH>>>(pool, gcnt, Wfc, bfc, out);
}

// round 15
// speedup vs baseline: 1.7252x; 1.1022x over previous
#include <cuda_runtime.h>
#include <cuda_bf16.h>
#include <cuda_fp16.h>
#include <math.h>
#include <stdint.h>

// ---------------- static scratch (no allocations allowed) ----------------
#define MAXN 100000
#define MAXE 1600000
#define NGRAPH 256

__device__ __half g_h1[(size_t)MAXN * 64];    // layer1 out (gather array)
__device__ __half g_t2[(size_t)MAXN * 64];    // agg2 out (GEMM23 input)
__device__ __half g_h3[(size_t)MAXN * 64];    // GEMM23 out (gather array)
__device__ __half g_w2h[128 * 64];            // W2 as [n][k] fp16 hi
__device__ __half g_w2l[128 * 64];            // W2 lo
__device__ __half g_w3h[64 * 128];            // W3 as [n][k] fp16 hi
__device__ __half g_w3l[64 * 128];            // W3 lo
__device__ float  g_xs[(size_t)MAXN * 5];
__device__ int    g_cnt[MAXN];                // zero-init; re-zeroed in scan3
__device__ int    g_rowptr[MAXN + 1];
__device__ int    g_curoff[MAXN];
__device__ float  g_dinv[MAXN];
__device__ int    g_col[MAXE];
__device__ int    g_bsums[128];
__device__ float  g_pool[NGRAPH * 64];
__device__ float  g_gcnt[NGRAPH];
__device__ int    g_is64[1];

__device__ __forceinline__ int load_idx(const void* p, long long i, int is64) {
    if (is64) return (int)((const long long*)p)[i];
    return ((const int*)p)[i];
}

__device__ __forceinline__ void mma16816h(float* d, const uint32_t* a,
                                          uint32_t b0, uint32_t b1) {
    asm volatile(
        "mma.sync.aligned.m16n8k16.row.col.f32.f16.f16.f32 "
        "{%0,%1,%2,%3}, {%4,%5,%6,%7}, {%8,%9}, {%0,%1,%2,%3};"
        : "+f"(d[0]), "+f"(d[1]), "+f"(d[2]), "+f"(d[3])
        : "r"(a[0]), "r"(a[1]), "r"(a[2]), "r"(a[3]), "r"(b0), "r"(b1));
}

// ---------------- degree count (+ per-block dtype detect) ----------------
__global__ void k_count(const void* __restrict__ ei, int E, int* cnt, int* flag) {
    __shared__ int any;
    if (threadIdx.x == 0) any = 0;
    __syncthreads();
    const int* probe = (const int*)ei;
    int loc = 0;
    for (int q = threadIdx.x; q < 512; q += blockDim.x)
        if (probe[2 * q + 1] != 0) loc = 1;
    if (loc) atomicOr(&any, 1);
    __syncthreads();
    int is64 = any ? 0 : 1;
    if (blockIdx.x == 0 && threadIdx.x == 0) flag[0] = is64;
    int e = blockIdx.x * blockDim.x + threadIdx.x;
    if (e < E) {
        int d = load_idx(ei, (long long)E + e, is64);
        atomicAdd(&cnt[d], 1);
    }
}

__global__ void k_scan1(const int* __restrict__ cnt, int* rowptr, int* bsums, int n) {
    __shared__ int s[1024];
    int i = blockIdx.x * 1024 + threadIdx.x;
    int v = (i < n) ? cnt[i] : 0;
    s[threadIdx.x] = v;
    __syncthreads();
    for (int off = 1; off < 1024; off <<= 1) {
        int t = 0;
        if ((int)threadIdx.x >= off) t = s[threadIdx.x - off];
        __syncthreads();
        s[threadIdx.x] += t;
        __syncthreads();
    }
    if (i < n) rowptr[i] = s[threadIdx.x] - v;
    if (threadIdx.x == 1023) bsums[blockIdx.x] = s[1023];
}

// scan finalize + dinv + x prescale + pool zero + cnt re-zero (fused)
__global__ void k_scan3(int* rowptr, int* curoff, const int* __restrict__ bsums,
                        int* cnt, float* dinv,
                        const float* __restrict__ x, float* xs,
                        float* pool, float* gcnt, int n, int E, int nb) {
    __shared__ int pb[128];
    __shared__ int ws[4];
    int t = threadIdx.x;
    int v = 0, orig = 0;
    if (t < 128) {
        v = (t < nb) ? bsums[t] : 0;
        orig = v;
#pragma unroll
        for (int off = 1; off < 32; off <<= 1) {
            int u = __shfl_up_sync(0xffffffffu, v, off);
            if ((t & 31) >= off) v += u;
        }
        if ((t & 31) == 31) ws[t >> 5] = v;
    }
    __syncthreads();
    if (t == 0) { int a = 0; for (int q = 0; q < 4; q++) { int xq = ws[q]; ws[q] = a; a += xq; } }
    __syncthreads();
    if (t < 128) pb[t] = v - orig + ws[t >> 5];
    __syncthreads();

    int i = blockIdx.x * blockDim.x + t;
    if (i < n) {
        int r = rowptr[i] + pb[i >> 10];
        rowptr[i] = r;
        curoff[i] = r;
        float d = rsqrtf((float)cnt[i] + 1.0f);
        cnt[i] = 0;
        dinv[i] = d;
#pragma unroll
        for (int k = 0; k < 5; k++) xs[(size_t)i * 5 + k] = d * x[(size_t)i * 5 + k];
    }
    if (i < NGRAPH * 64) pool[i] = 0.f;
    if (i < NGRAPH) gcnt[i] = 0.f;
    if (i == 0) rowptr[n] = E;
}

// CSR fill; extra blocks (>= eb) pre-convert W2/W3 to fp16 hi/lo [n][k].
__global__ void k_fill(const void* __restrict__ ei, int E, int eb,
                       int* curoff, int* col, const int* flag,
                       const float* __restrict__ W2, const float* __restrict__ W3,
                       __half* w2h, __half* w2l, __half* w3h, __half* w3l) {
    if ((int)blockIdx.x >= eb) {
        int idx = (blockIdx.x - eb) * 256 + threadIdx.x;   // 0..16383
        if (idx < 8192) {                                   // W2: [64][128] -> [n=128][k=64]
            int nrow = idx % 128;
            int k = idx / 128;
            float w = __ldg(&W2[(size_t)k * 128 + nrow]);
            __half h = __float2half_rn(w);
            __half l = __float2half_rn(w - __half2float(h));
            w2h[nrow * 64 + k] = h;
            w2l[nrow * 64 + k] = l;
        } else {                                            // W3: [128][64] -> [n=64][k=128]
            int j = idx - 8192;
            int nrow = j % 64;
            int k = j / 64;
            float w = __ldg(&W3[(size_t)k * 64 + nrow]);
            __half h = __float2half_rn(w);
            __half l = __float2half_rn(w - __half2float(h));
            w3h[nrow * 128 + k] = h;
            w3l[nrow * 128 + k] = l;
        }
        return;
    }
    int is64 = flag[0];
    int e = blockIdx.x * blockDim.x + threadIdx.x;
    if (e >= E) return;
    int s = load_idx(ei, e, is64);
    int d = load_idx(ei, (long long)E + e, is64);
    int p = atomicAdd(&curoff[d], 1);
    col[p] = s;
}

// ---------------- fused layer1: agg(xs) + GEMM(5->64) + relu -> fp16 --------
__global__ void k_l1(const float* __restrict__ xs,
                     const int* __restrict__ rowptr, const int* __restrict__ col,
                     const float* __restrict__ dinv,
                     const float* __restrict__ W1, const float* __restrict__ b1,
                     __half* __restrict__ out, int n) {
    __shared__ float Ws[5 * 64];
    __shared__ float bs[64];
    int t = threadIdx.x;
    for (int i = t; i < 5 * 64; i += 256) Ws[i] = W1[i];
    if (t < 64) bs[t] = b1[t];
    __syncthreads();

    int gt = blockIdx.x * 256 + t;
    int node = gt >> 3;
    int f = gt & 7;
    bool live = (node < n);
    int nodec = live ? node : (n - 1);

    int beg = rowptr[nodec], end = rowptr[nodec + 1];
    bool valid = (f < 5);
    float acc = 0.f;
    int e = beg;
    for (; e + 3 < end; e += 4) {
        int s0 = col[e], s1 = col[e + 1], s2 = col[e + 2], s3 = col[e + 3];
        float v0 = 0.f, v1 = 0.f, v2 = 0.f, v3 = 0.f;
        if (valid) {
            v0 = __ldg(&xs[(size_t)s0 * 5 + f]);
            v1 = __ldg(&xs[(size_t)s1 * 5 + f]);
            v2 = __ldg(&xs[(size_t)s2 * 5 + f]);
            v3 = __ldg(&xs[(size_t)s3 * 5 + f]);
        }
        acc += (v0 + v1) + (v2 + v3);
    }
    for (; e < end; e++) {
        int s = col[e];
        if (valid) acc += __ldg(&xs[(size_t)s * 5 + f]);
    }
    float ds = dinv[nodec];
    if (valid) acc = ds * (acc + xs[(size_t)nodec * 5 + f]);

    float v[5];
#pragma unroll
    for (int k = 0; k < 5; k++) v[k] = __shfl_sync(0xffffffffu, acc, k, 8);

    int cb = f * 8;
    float o[8];
#pragma unroll
    for (int j = 0; j < 8; j++) {
        float a = bs[cb + j];
#pragma unroll
        for (int k = 0; k < 5; k++) a += v[k] * Ws[k * 64 + cb + j];
        o[j] = fmaxf(a, 0.f) * ds;
    }
    if (live) {
        __half2 q0 = __float22half2_rn(make_float2(o[0], o[1]));
        __half2 q1 = __float22half2_rn(make_float2(o[2], o[3]));
        __half2 q2 = __float22half2_rn(make_float2(o[4], o[5]));
        __half2 q3 = __float22half2_rn(make_float2(o[6], o[7]));
        uint4 u;
        u.x = *(uint32_t*)&q0; u.y = *(uint32_t*)&q1;
        u.z = *(uint32_t*)&q2; u.w = *(uint32_t*)&q3;
        *reinterpret_cast<uint4*>(&out[(size_t)node * 64 + cb]) = u;
    }
}

// ---------------- agg width 64 on fp16 (no pool): warp/node ----------------
__global__ void k_agg64h(const __half2* __restrict__ h,
                         const int* __restrict__ rowptr, const int* __restrict__ col,
                         const float* __restrict__ dinv,
                         __half2* __restrict__ out, int n) {
    int node = blockIdx.x * 8 + (threadIdx.x >> 5);
    int lane = threadIdx.x & 31;
    if (node >= n) return;
    int beg = rowptr[node], end = rowptr[node + 1];
    float a0 = 0.f, a1 = 0.f;
    int e = beg;
    for (; e + 3 < end; e += 4) {
        int s0 = col[e], s1 = col[e + 1], s2 = col[e + 2], s3 = col[e + 3];
        float2 f0 = __half22float2(__ldg(&h[(size_t)s0 * 32 + lane]));
        float2 f1 = __half22float2(__ldg(&h[(size_t)s1 * 32 + lane]));
        float2 f2 = __half22float2(__ldg(&h[(size_t)s2 * 32 + lane]));
        float2 f3 = __half22float2(__ldg(&h[(size_t)s3 * 32 + lane]));
        a0 += (f0.x + f1.x) + (f2.x + f3.x);
        a1 += (f0.y + f1.y) + (f2.y + f3.y);
    }
    for (; e < end; e++) {
        int s = col[e];
        float2 f = __half22float2(__ldg(&h[(size_t)s * 32 + lane]));
        a0 += f.x;
        a1 += f.y;
    }
    float2 self = __half22float2(h[(size_t)node * 32 + lane]);
    float ds = dinv[node];
    a0 = ds * (a0 + self.x);
    a1 = ds * (a1 + self.y);
    out[(size_t)node * 32 + lane] = __float22half2_rn(make_float2(a0, a1));
}

// ---------------- agg + bias + relu + mean-pool, smem-reduced atomics -------
__global__ void k_aggpool(const __half2* __restrict__ h,
                          const int* __restrict__ rowptr, const int* __restrict__ col,
                          const float* __restrict__ dinv,
                          const float* __restrict__ bias,
                          const void* __restrict__ batch, const int* flag,
                          float* pool, float* gcnt, int n) {
    __shared__ float acc[2][64];
    __shared__ int sg[8];
    int wid = threadIdx.x >> 5;
    int lane = threadIdx.x & 31;
    int node = blockIdx.x * 8 + wid;
    bool live = node < n;

    float a0 = 0.f, a1 = 0.f;
    int g = -1;
    if (live) {
        int beg = rowptr[node], end = rowptr[node + 1];
        int e = beg;
        for (; e + 3 < end; e += 4) {
            int s0 = col[e], s1 = col[e + 1], s2 = col[e + 2], s3 = col[e + 3];
            float2 f0 = __half22float2(__ldg(&h[(size_t)s0 * 32 + lane]));
            float2 f1 = __half22float2(__ldg(&h[(size_t)s1 * 32 + lane]));
            float2 f2 = __half22float2(__ldg(&h[(size_t)s2 * 32 + lane]));
            float2 f3 = __half22float2(__ldg(&h[(size_t)s3 * 32 + lane]));
            a0 += (f0.x + f1.x) + (f2.x + f3.x);
            a1 += (f0.y + f1.y) + (f2.y + f3.y);
        }
        for (; e < end; e++) {
            int s = col[e];
            float2 f = __half22float2(__ldg(&h[(size_t)s * 32 + lane]));
            a0 += f.x;
            a1 += f.y;
        }
        float2 self = __half22float2(h[(size_t)node * 32 + lane]);
        float ds = dinv[node];
        a0 = fmaxf(ds * (a0 + self.x) + __ldg(&bias[2 * lane]), 0.f);
        a1 = fmaxf(ds * (a1 + self.y) + __ldg(&bias[2 * lane + 1]), 0.f);
        g = load_idx(batch, node, flag[0]);
    }
    if (lane == 0) sg[wid] = live ? g : -1;
    for (int i = threadIdx.x; i < 128; i += 256) acc[i >> 6][i & 63] = 0.f;
    __syncthreads();

    int gmin = 0x7fffffff, gmax = -1;
#pragma unroll
    for (int w = 0; w < 8; w++) {
        int gg = sg[w];
        if (gg >= 0) { gmin = min(gmin, gg); gmax = max(gmax, gg); }
    }
    bool fast = (gmax >= 0) && (gmax - gmin <= 1);

    if (live) {
        if (fast) {
            atomicAdd(&acc[g - gmin][2 * lane], a0);
            atomicAdd(&acc[g - gmin][2 * lane + 1], a1);
        } else {
            atomicAdd(&pool[g * 64 + 2 * lane], a0);
            atomicAdd(&pool[g * 64 + 2 * lane + 1], a1);
            if (lane == 0) atomicAdd(&gcnt[g], 1.0f);
        }
    }
    __syncthreads();
    if (fast) {
        int t = threadIdx.x;
        if (t < 128) {
            int r = t >> 6, f = t & 63;
            if (gmin + r <= gmax) {
                float v = acc[r][f];
                atomicAdd(&pool[(gmin + r) * 64 + f], v);
            }
        }
        if (t < 2 && gmin + t <= gmax) {
            int c = 0;
#pragma unroll
            for (int w = 0; w < 8; w++) if (sg[w] == gmin + (int)t) c++;
            if (c > 0) atomicAdd(&gcnt[gmin + t], (float)c);
        }
    }
}

// ---------------- fused GEMM2+GEMM3 (fp16 MMA, 2-term weights) --------------
// h3 = ( relu(t2 @ W2 + b2) @ W3 ) * dinv, per 128-row tile.
// smem: B2h/B2l [128][72], B3h/B3l [64][136], U = As[128][72] then H2[128][136].
#define G23_SMEM ((2 * 128 * 72 + 2 * 64 * 136 + 128 * 136) * 2)
__launch_bounds__(256)
__global__ void k_gemm23(const __half* __restrict__ A,
                         const __half* __restrict__ w2h, const __half* __restrict__ w2l,
                         const __half* __restrict__ w3h, const __half* __restrict__ w3l,
                         const float* __restrict__ b2, const float* __restrict__ dinv,
                         __half* __restrict__ out, int n) {
    constexpr int P2 = 72, P3 = 136;
    extern __shared__ char sm[];
    uint16_t* B2h = (uint16_t*)sm;
    uint16_t* B2l = B2h + 128 * P2;
    uint16_t* B3h = B2l + 128 * P2;
    uint16_t* B3l = B3h + 64 * P3;
    uint16_t* U   = B3l + 64 * P3;   // As [128][P2] then H2 [128][P3]

    const int tid = threadIdx.x;
    const int nodeBase = blockIdx.x * 128;

    // load A tile (fp16 direct) into U as As[128][P2]
    for (int q = tid; q < 128 * 8; q += 256) {
        int r = q >> 3;
        int c8 = (q & 7) * 8;
        int gn = nodeBase + r;
        uint4 v = make_uint4(0u, 0u, 0u, 0u);
        if (gn < n) v = *reinterpret_cast<const uint4*>(&A[(size_t)gn * 64 + c8]);
        *reinterpret_cast<uint4*>(&U[r * P2 + c8]) = v;
    }
    // load W2 hi/lo [128][64] -> pitch P2
    for (int q = tid; q < 128 * 8; q += 256) {
        int nrow = q >> 3;
        int c8 = (q & 7) * 8;
        *reinterpret_cast<uint4*>(&B2h[nrow * P2 + c8]) =
            *reinterpret_cast<const uint4*>(&w2h[(size_t)nrow * 64 + c8]);
        *reinterpret_cast<uint4*>(&B2l[nrow * P2 + c8]) =
            *reinterpret_cast<const uint4*>(&w2l[(size_t)nrow * 64 + c8]);
    }
    // load W3 hi/lo [64][128] -> pitch P3
    for (int q = tid; q < 64 * 16; q += 256) {
        int nrow = q >> 4;
        int c8 = (q & 15) * 8;
        *reinterpret_cast<uint4*>(&B3h[nrow * P3 + c8]) =
            *reinterpret_cast<const uint4*>(&w3h[(size_t)nrow * 128 + c8]);
        *reinterpret_cast<uint4*>(&B3l[nrow * P3 + c8]) =
            *reinterpret_cast<const uint4*>(&w3l[(size_t)nrow * 128 + c8]);
    }
    __syncthreads();

    const int wid = tid >> 5;
    const int lane = tid & 31;
    const int g = lane >> 2;
    const int t4 = lane & 3;
    const int warpRow = wid * 16;

    // ---- stage 1: H2 = relu(As @ W2^T-layout + b2), NC=128 ----
    float acc1[16][4];
#pragma unroll
    for (int nt = 0; nt < 16; nt++)
#pragma unroll
        for (int j = 0; j < 4; j++) acc1[nt][j] = 0.f;

#pragma unroll
    for (int ks = 0; ks < 4; ks++) {
        int k0 = ks * 16;
        int r0 = warpRow + g;
        uint32_t af[4];
        af[0] = *(uint32_t*)&U[r0 * P2 + k0 + 2 * t4];
        af[1] = *(uint32_t*)&U[(r0 + 8) * P2 + k0 + 2 * t4];
        af[2] = *(uint32_t*)&U[r0 * P2 + k0 + 2 * t4 + 8];
        af[3] = *(uint32_t*)&U[(r0 + 8) * P2 + k0 + 2 * t4 + 8];
#pragma unroll
        for (int nt = 0; nt < 16; nt++) {
            int nr = nt * 8 + g;
            uint32_t bh0 = *(uint32_t*)&B2h[nr * P2 + k0 + 2 * t4];
            uint32_t bh1 = *(uint32_t*)&B2h[nr * P2 + k0 + 2 * t4 + 8];
            uint32_t bl0 = *(uint32_t*)&B2l[nr * P2 + k0 + 2 * t4];
            uint32_t bl1 = *(uint32_t*)&B2l[nr * P2 + k0 + 2 * t4 + 8];
            mma16816h(acc1[nt], af, bh0, bh1);
            mma16816h(acc1[nt], af, bl0, bl1);
        }
    }
    __syncthreads();   // all As reads done; U becomes H2 [128][P3]

    {
        int r0 = warpRow + g;
#pragma unroll
        for (int nt = 0; nt < 16; nt++) {
            int colc = nt * 8 + 2 * t4;
            float b0 = __ldg(&b2[colc]);
            float b1 = __ldg(&b2[colc + 1]);
            __half2 h0 = __float22half2_rn(make_float2(
                fmaxf(acc1[nt][0] + b0, 0.f), fmaxf(acc1[nt][1] + b1, 0.f)));
            __half2 h1 = __float22half2_rn(make_float2(
                fmaxf(acc1[nt][2] + b0, 0.f), fmaxf(acc1[nt][3] + b1, 0.f)));
            *(uint32_t*)&U[r0 * P3 + colc] = *(uint32_t*)&h0;
            *(uint32_t*)&U[(r0 + 8) * P3 + colc] = *(uint32_t*)&h1;
        }
    }
    __syncthreads();

    // ---- stage 2: out = (H2 @ W3^T-layout) * dinv, NC=64, K=128 ----
    float acc2[8][4];
#pragma unroll
    for (int nt = 0; nt < 8; nt++)
#pragma unroll
        for (int j = 0; j < 4; j++) acc2[nt][j] = 0.f;

#pragma unroll
    for (int ks = 0; ks < 8; ks++) {
        int k0 = ks * 16;
        int r0 = warpRow + g;
        uint32_t af[4];
        af[0] = *(uint32_t*)&U[r0 * P3 + k0 + 2 * t4];
        af[1] = *(uint32_t*)&U[(r0 + 8) * P3 + k0 + 2 * t4];
        af[2] = *(uint32_t*)&U[r0 * P3 + k0 + 2 * t4 + 8];
        af[3] = *(uint32_t*)&U[(r0 + 8) * P3 + k0 + 2 * t4 + 8];
#pragma unroll
        for (int nt = 0; nt < 8; nt++) {
            int nr = nt * 8 + g;
            uint32_t bh0 = *(uint32_t*)&B3h[nr * P3 + k0 + 2 * t4];
            uint32_t bh1 = *(uint32_t*)&B3h[nr * P3 + k0 + 2 * t4 + 8];
            uint32_t bl0 = *(uint32_t*)&B3l[nr * P3 + k0 + 2 * t4];
            uint32_t bl1 = *(uint32_t*)&B3l[nr * P3 + k0 + 2 * t4 + 8];
            mma16816h(acc2[nt], af, bh0, bh1);
            mma16816h(acc2[nt], af, bl0, bl1);
        }
    }

    int row0 = nodeBase + warpRow + g;
    int row1 = row0 + 8;
    bool l0 = row0 < n, l1 = row1 < n;
    float ds0 = l0 ? dinv[row0] : 1.0f;
    float ds1 = l1 ? dinv[row1] : 1.0f;
#pragma unroll
    for (int nt = 0; nt < 8; nt++) {
        int colc = nt * 8 + 2 * t4;
        if (l0) {
            __half2 hh = __float22half2_rn(make_float2(acc2[nt][0] * ds0, acc2[nt][1] * ds0));
            *(uint32_t*)&out[(size_t)row0 * 64 + colc] = *(uint32_t*)&hh;
        }
        if (l1) {
            __half2 hh = __float22half2_rn(make_float2(acc2[nt][2] * ds1, acc2[nt][3] * ds1));
            *(uint32_t*)&out[(size_t)row1 * 64 + colc] = *(uint32_t*)&hh;
        }
    }
}

// ---------------- final FC + sigmoid ----------------
__global__ void k_final(const float* __restrict__ pool, const float* __restrict__ gcnt,
                        const float* __restrict__ Wfc, const float* __restrict__ bfc,
                        float* __restrict__ out) {
    int g = threadIdx.x;
    float c = fmaxf(gcnt[g], 1.0f);
    float acc = 0.f;
#pragma unroll
    for (int k = 0; k < 64; k++) acc += pool[g * 64 + k] * Wfc[k];
    acc = acc / c + bfc[0];
    out[g] = 1.f / (1.f + expf(-acc));
}

// ---------------- launch ----------------
extern "C" void kernel_launch(void* const* d_in, const int* in_sizes, int n_in,
                              void* d_out, int out_size) {
    const float*  x     = (const float*)d_in[0];
    const void*   ei    = d_in[1];
    const void*   batch = d_in[2];
    const float*  W1    = (const float*)d_in[3];
    const float*  b1    = (const float*)d_in[4];
    const float*  W2    = (const float*)d_in[5];
    const float*  b2    = (const float*)d_in[6];
    const float*  W3    = (const float*)d_in[7];
    const float*  b3    = (const float*)d_in[8];
    const float*  Wfc   = (const float*)d_in[9];
    const float*  bfc   = (const float*)d_in[10];
    float*        out   = (float*)d_out;

    const int N = in_sizes[0] / 5;
    const int E = in_sizes[1] / 2;

    float *xs, *dinv, *pool, *gcnt;
    __half *h1, *t2, *h3, *w2h, *w2l, *w3h, *w3l;
    int *cnt, *rowptr, *curoff, *col, *bsums, *is64;
    cudaGetSymbolAddress((void**)&h1, g_h1);
    cudaGetSymbolAddress((void**)&t2, g_t2);
    cudaGetSymbolAddress((void**)&h3, g_h3);
    cudaGetSymbolAddress((void**)&w2h, g_w2h);
    cudaGetSymbolAddress((void**)&w2l, g_w2l);
    cudaGetSymbolAddress((void**)&w3h, g_w3h);
    cudaGetSymbolAddress((void**)&w3l, g_w3l);
    cudaGetSymbolAddress((void**)&xs, g_xs);
    cudaGetSymbolAddress((void**)&dinv, g_dinv);
    cudaGetSymbolAddress((void**)&pool, g_pool);
    cudaGetSymbolAddress((void**)&gcnt, g_gcnt);
    cudaGetSymbolAddress((void**)&cnt, g_cnt);
    cudaGetSymbolAddress((void**)&rowptr, g_rowptr);
    cudaGetSymbolAddress((void**)&curoff, g_curoff);
    cudaGetSymbolAddress((void**)&col, g_col);
    cudaGetSymbolAddress((void**)&bsums, g_bsums);
    cudaGetSymbolAddress((void**)&is64, g_is64);

    static int smem_set = 0;
    if (!smem_set) {
        cudaFuncSetAttribute(k_gemm23, cudaFuncAttributeMaxDynamicSharedMemorySize, G23_SMEM);
        smem_set = 1;
    }

    const int TB = 256;
    k_count<<<(E + TB - 1) / TB, TB>>>(ei, E, cnt, is64);

    int nb = (N + 1023) / 1024;
    k_scan1<<<nb, 1024>>>(cnt, rowptr, bsums, N);
    k_scan3<<<(N + TB - 1) / TB, TB>>>(rowptr, curoff, bsums, cnt, dinv, x, xs,
                                       pool, gcnt, N, E, nb);
    int eb = (E + TB - 1) / TB;
    k_fill<<<eb + 64, TB>>>(ei, E, eb, curoff, col, is64, W2, W3, w2h, w2l, w3h, w3l);

    // L1 fused: agg5 + GEMM(5->64) + relu, prescaled -> h1 (fp16)
    k_l1<<<(N * 8 + TB - 1) / TB, TB>>>(xs, rowptr, col, dinv, W1, b1, h1, N);

    // L2 agg -> t2 (fp16)
    k_agg64h<<<(N + 7) / 8, TB>>>((const __half2*)h1, rowptr, col, dinv,
                                  (__half2*)t2, N);

    // fused GEMM2+relu+GEMM3 (*dinv) -> h3 (fp16)
    int gtc = (N + 127) / 128;
    k_gemm23<<<gtc, 256, G23_SMEM>>>(t2, w2h, w2l, w3h, w3l, b2, dinv, h3, N);

    // L3 agg + b3 + relu + pool (reduced atomics)
    k_aggpool<<<(N + 7) / 8, TB>>>((const __half2*)h3, rowptr, col, dinv, b3,
                                   batch, is64, pool, gcnt, N);

    k_final<<<1, NGRAPH>>>(pool, gcnt, Wfc, bfc, out);
}